// round 9
// baseline (speedup 1.0000x reference)
#include <cuda_runtime.h>
#include <cuda_fp16.h>
#include <math.h>
#include <stdint.h>

#define NN 2048
#define BB 256
#define DD 512
#define MAXIT 300

// ---- solve: 16 m-tiles x 4 n-tiles = 64 CTAs, MT=128 NT=64 -----------------
#define SB 64
#define KC 64            // k per stage (64 fp16 = 128B rows)
#define NSTG 4
#define A_BYTES (128*128)   // 16KB: 128 rows x 128B
#define B_BYTES (64*128)    // 8KB
#define STGB (A_BYTES + B_BYTES)
#define O_A 0
#define O_B A_BYTES
#define DYN_SMEM (NSTG*STGB + 128)
#define NKC (NN/KC)      // 32

// ---- build_w tiling --------------------------------------------------------
#define WNSTG 3
#define WMAT (128*128)      // 16KB per matrix tile
#define WSTG (2*WMAT)
#define WDYN (WNSTG*WSTG + 128)

__device__ __half  g_Wh[NN*NN];      // 8MB fp16 W
__device__ __half  g_Ath[NN*NN];     // 8MB fp16 A^T
__device__ float   g_Vx[NN*BB];      // [i][j]
__device__ __half  g_zh[2][BB*NN];   // fp16 z, [j][k], ping-pong
__device__ double  g_nd[3][2];
__device__ unsigned g_arrive, g_release;

__device__ __forceinline__ uint32_t smem_u32(const void* p) {
    uint32_t a;
    asm("{ .reg .u64 t; cvta.to.shared.u64 t, %1; cvt.u32.u64 %0, t; }" : "=r"(a) : "l"(p));
    return a;
}
__device__ __forceinline__ void cp16(uint32_t dst, const void* src) {
    asm volatile("cp.async.cg.shared.global [%0], [%1], 16;" :: "r"(dst), "l"(src) : "memory");
}
#define CP_COMMIT() asm volatile("cp.async.commit_group;" ::: "memory")
#define CP_WAIT(n)  asm volatile("cp.async.wait_group %0;" :: "n"(n) : "memory")
__device__ __forceinline__ void ldsm4(uint32_t* r, uint32_t a) {
    asm volatile("ldmatrix.sync.aligned.m8n8.x4.shared.b16 {%0,%1,%2,%3}, [%4];"
                 : "=r"(r[0]), "=r"(r[1]), "=r"(r[2]), "=r"(r[3]) : "r"(a));
}
__device__ __forceinline__ void mma_hf(float* c, const uint32_t* a, uint32_t b0, uint32_t b1) {
    asm volatile("mma.sync.aligned.m16n8k16.row.col.f32.f16.f16.f32 "
                 "{%0,%1,%2,%3}, {%4,%5,%6,%7}, {%8,%9}, {%0,%1,%2,%3};"
                 : "+f"(c[0]), "+f"(c[1]), "+f"(c[2]), "+f"(c[3])
                 : "r"(a[0]), "r"(a[1]), "r"(a[2]), "r"(a[3]), "r"(b0), "r"(b1));
}

__global__ void init_kernel() {
    int idx = blockIdx.x * blockDim.x + threadIdx.x;
    if (idx < BB * NN) g_zh[0][idx] = __float2half(0.0f);
    if (idx == 0) {
        for (int i = 0; i < 3; i++) { g_nd[i][0] = 0.0; g_nd[i][1] = 0.0; }
        g_arrive = 0u; g_release = 0u;
    }
}

// At[i][k] = A[k][i] in fp16
__global__ void __launch_bounds__(256) split_at_kernel(const float* __restrict__ A) {
    __shared__ float t[32][33];
    const int i0 = blockIdx.x * 32, k0 = blockIdx.y * 32;
    const int lx = threadIdx.x & 31, ly = threadIdx.x >> 5;
#pragma unroll
    for (int r = 0; r < 32; r += 8)
        t[ly + r][lx] = A[(long)(k0 + ly + r) * NN + i0 + lx];
    __syncthreads();
#pragma unroll
    for (int r = 0; r < 32; r += 8)
        g_Ath[(long)(i0 + ly + r) * NN + k0 + lx] = __float2half_rn(t[lx][ly + r]);
}

// W = (1-m)I - At At^T + S - S^T  (fp16 mma), output fp16
__global__ void __launch_bounds__(256, 1) build_w_mma_kernel(const float* __restrict__ S,
                                                             const float* __restrict__ m_raw) {
    extern __shared__ __align__(16) char dsm[];
    const uint32_t sbase = (smem_u32(dsm) + 127u) & ~127u;
    const int tid = threadIdx.x, l = tid & 31, warp = tid >> 5;
    const int i0 = blockIdx.x * 128, j0 = blockIdx.y * 128;
    const int wm = (warp >> 2) * 64, wn = (warp & 3) * 32;
    const int r7 = l & 7;
    const int rowA = wm + r7 + ((l >> 3) & 1) * 8;
    const int kgA = (l >> 4) & 1;
    const int rowBb = wn + r7 + ((l >> 4) & 1) * 8;
    const int kgB = (l >> 3) & 1;

    float c[4][4][4];
#pragma unroll
    for (int f = 0; f < 4; f++)
#pragma unroll
        for (int g = 0; g < 4; g++)
#pragma unroll
            for (int q = 0; q < 4; q++) c[f][g][q] = 0.0f;

#define W_LOAD(stg, k0v) do {                                                 \
    const uint32_t sb_ = sbase + (stg) * WSTG;                                \
    _Pragma("unroll")                                                         \
    for (int rep = 0; rep < 4; rep++) {                                       \
        const int idx_ = tid + rep * 256;                                     \
        const int r_ = idx_ >> 3, c_ = idx_ & 7;                              \
        const uint32_t d_ = (uint32_t)r_ * 128 + ((uint32_t)(c_ ^ (r_ & 7)) << 4); \
        cp16(sb_ + 0*WMAT + d_, g_Ath + (long)(i0 + r_) * NN + (k0v) + c_ * 8); \
        cp16(sb_ + 1*WMAT + d_, g_Ath + (long)(j0 + r_) * NN + (k0v) + c_ * 8); \
    } } while (0)

#pragma unroll
    for (int s = 0; s < WNSTG - 1; s++) { W_LOAD(s, s * KC); CP_COMMIT(); }

    for (int kc = 0; kc < NKC; kc++) {
        CP_WAIT(WNSTG - 2);
        __syncthreads();
        if (kc + WNSTG - 1 < NKC) W_LOAD((kc + WNSTG - 1) % WNSTG, (kc + WNSTG - 1) * KC);
        CP_COMMIT();
        const uint32_t sb = sbase + (kc % WNSTG) * WSTG;
#pragma unroll
        for (int s4 = 0; s4 < 4; s4++) {
            const int kg0 = s4 * 2;
            const uint32_t swA = (uint32_t)((kg0 + kgA) ^ r7) << 4;
            const uint32_t swB = (uint32_t)((kg0 + kgB) ^ r7) << 4;
            uint32_t ah[4][4], bh[2][4];
#pragma unroll
            for (int f = 0; f < 4; f++)
                ldsm4(ah[f], sb + 0*WMAT + (uint32_t)(rowA + f * 16) * 128 + swA);
#pragma unroll
            for (int g2 = 0; g2 < 2; g2++)
                ldsm4(bh[g2], sb + 1*WMAT + (uint32_t)(rowBb + g2 * 16) * 128 + swB);
#pragma unroll
            for (int f = 0; f < 4; f++)
#pragma unroll
                for (int g2 = 0; g2 < 2; g2++) {
                    mma_hf(c[f][g2*2+0], ah[f], bh[g2][0], bh[g2][1]);
                    mma_hf(c[f][g2*2+1], ah[f], bh[g2][2], bh[g2][3]);
                }
        }
    }
#undef W_LOAD

    const float m = log1pf(expf(m_raw[0]));
    const float omm = 1.0f - m;
#pragma unroll
    for (int f = 0; f < 4; f++)
#pragma unroll
        for (int g = 0; g < 4; g++)
#pragma unroll
            for (int h = 0; h < 2; h++) {
                const int i = i0 + wm + f * 16 + h * 8 + (l >> 2);
                const int j = j0 + wn + g * 8 + (l & 3) * 2;
                float2 sij = *(const float2*)&S[(long)i * NN + j];
                float w0 = -c[f][g][h*2+0] + sij.x - S[(long)j * NN + i];
                float w1 = -c[f][g][h*2+1] + sij.y - S[(long)(j + 1) * NN + i];
                if (i == j) w0 += omm;
                if (i == j + 1) w1 += omm;
                *(__half2*)&g_Wh[(long)i * NN + j] = __floats2half2_rn(w0, w1);
            }
}

#define TMW 64
#define KTW 16
#define PADW 68
__global__ void __launch_bounds__(256) build_vx_kernel(const float* __restrict__ U,
                                                       const float* __restrict__ b,
                                                       const float* __restrict__ x) {
    __shared__ __align__(16) float Us[KTW][PADW];
    __shared__ __align__(16) float Xs[KTW][PADW];
    const int i0 = blockIdx.x * TMW, j0 = blockIdx.y * TMW;
    const int tx = threadIdx.x & 15, ty = threadIdx.x >> 4;
    float acc[4][4];
#pragma unroll
    for (int a = 0; a < 4; a++)
#pragma unroll
        for (int cc = 0; cc < 4; cc++) acc[a][cc] = 0.0f;
    for (int k0 = 0; k0 < DD; k0 += KTW) {
#pragma unroll
        for (int t = threadIdx.x; t < KTW * TMW; t += 256) {
            int rr = t >> 4, cc = t & 15;
            Us[cc][rr] = U[(i0 + rr) * DD + k0 + cc];
            Xs[cc][rr] = x[(j0 + rr) * DD + k0 + cc];
        }
        __syncthreads();
#pragma unroll
        for (int k = 0; k < KTW; k++) {
            float4 av = *(const float4*)&Us[k][ty * 4];
            float4 bv = *(const float4*)&Xs[k][tx * 4];
            float am[4] = {av.x, av.y, av.z, av.w};
            float bn[4] = {bv.x, bv.y, bv.z, bv.w};
#pragma unroll
            for (int mi = 0; mi < 4; mi++)
#pragma unroll
                for (int ni = 0; ni < 4; ni++) acc[mi][ni] += am[mi] * bn[ni];
        }
        __syncthreads();
    }
#pragma unroll
    for (int mi = 0; mi < 4; mi++) {
        const int i = i0 + ty * 4 + mi;
        const float bi = b[i];
#pragma unroll
        for (int ni = 0; ni < 4; ni++)
            g_Vx[i * BB + j0 + tx * 4 + ni] = acc[mi][ni] + bi;
    }
}

__device__ __forceinline__ void grid_barrier(unsigned& gen) {
    __syncthreads();
    if (threadIdx.x == 0) {
        gen++;
        __threadfence();
        unsigned prev = atomicAdd(&g_arrive, 1u);
        if (prev == SB - 1) {
            atomicExch(&g_arrive, 0u);
            __threadfence();
            atomicExch(&g_release, gen);
        } else {
            while (*(volatile unsigned*)&g_release < gen) { }
            __threadfence();
        }
    }
    __syncthreads();
}

// ---------------- persistent fp16 solver, MT=128 NT=64, 64 CTAs -------------
__global__ void __launch_bounds__(256, 1) solve_kernel(float* __restrict__ out) {
    extern __shared__ __align__(16) char dsm[];
    const uint32_t sbase = (smem_u32(dsm) + 127u) & ~127u;
    __shared__ float sredD[8], sredN[8];

    const int tid = threadIdx.x, l = tid & 31, warp = tid >> 5;
    const int i0 = (blockIdx.x >> 2) * 128, j0 = (blockIdx.x & 3) * 64;
    const int wm = (warp >> 1) * 32, wn = (warp & 1) * 32;
    const int r7 = l & 7;
    const int rA8 = ((l >> 3) & 1) * 8, selA = (l >> 4) & 1;
    const int rB8 = ((l >> 4) & 1) * 8, selB = (l >> 3) & 1;

    // fp32 z state in registers: [f(m16)][g(n8)][h(+8rows)][pair]
    float zr[2][4][2][2];
#pragma unroll
    for (int f = 0; f < 2; f++)
#pragma unroll
        for (int g = 0; g < 4; g++)
#pragma unroll
            for (int h = 0; h < 2; h++) { zr[f][g][h][0] = 0.0f; zr[f][g][h][1] = 0.0f; }

#define A_LOAD(stg, k0v) do {                                                 \
    const uint32_t sb_ = sbase + (stg) * STGB + O_A;                          \
    _Pragma("unroll")                                                         \
    for (int rep = 0; rep < 4; rep++) {                                       \
        const int idx_ = tid + rep * 256;                                     \
        const int r_ = idx_ >> 3, c_ = idx_ & 7;                              \
        cp16(sb_ + (uint32_t)r_ * 128 + ((uint32_t)(c_ ^ (r_ & 7)) << 4),     \
             g_Wh + (long)(i0 + r_) * NN + (k0v) + c_ * 8);                   \
    } } while (0)
#define B_LOAD(stg, k0v, zp) do {                                             \
    const uint32_t sb_ = sbase + (stg) * STGB + O_B;                          \
    _Pragma("unroll")                                                         \
    for (int rep = 0; rep < 2; rep++) {                                       \
        const int idx_ = tid + rep * 256;                                     \
        const int r_ = idx_ >> 3, c_ = idx_ & 7;                              \
        cp16(sb_ + (uint32_t)r_ * 128 + ((uint32_t)(c_ ^ (r_ & 7)) << 4),     \
             (zp) + (long)(j0 + r_) * NN + (k0v) + c_ * 8);                   \
    } } while (0)

    unsigned gen = 0;
    int cur = 0, it = 0;

    // W prefetch for iteration 1 (stages 0..2), one group
    A_LOAD(0, 0); A_LOAD(1, KC); A_LOAD(2, 2 * KC); CP_COMMIT();

    while (1) {
        it++;
        const __half* __restrict__ zp = g_zh[cur];
        float c[2][4][4];
#pragma unroll
        for (int f = 0; f < 2; f++)
#pragma unroll
            for (int g = 0; g < 4; g++)
#pragma unroll
                for (int q = 0; q < 4; q++) c[f][g][q] = 0.0f;

        // z loads for prefetched stages
#pragma unroll
        for (int s = 0; s < NSTG - 1; s++) { B_LOAD(s, s * KC, zp); CP_COMMIT(); }

        for (int kc = 0; kc < NKC; kc++) {
            CP_WAIT(2);
            __syncthreads();
            if (kc + NSTG - 1 < NKC) {
                A_LOAD((kc + NSTG - 1) & 3, (kc + NSTG - 1) * KC);
                B_LOAD((kc + NSTG - 1) & 3, (kc + NSTG - 1) * KC, zp);
            }
            CP_COMMIT();
            const uint32_t sb = sbase + (kc & 3) * STGB;
#pragma unroll
            for (int s4 = 0; s4 < 4; s4++) {
                const int kg0 = s4 * 2;
                const uint32_t swA = (uint32_t)((kg0 + selA) ^ r7) << 4;
                const uint32_t swB = (uint32_t)((kg0 + selB) ^ r7) << 4;
                uint32_t ah0[4], ah1[4], bh0[4], bh1[4];
                ldsm4(ah0, sb + O_A + (uint32_t)(wm + r7 + rA8) * 128 + swA);
                ldsm4(ah1, sb + O_A + (uint32_t)(wm + 16 + r7 + rA8) * 128 + swA);
                ldsm4(bh0, sb + O_B + (uint32_t)(wn + r7 + rB8) * 128 + swB);
                ldsm4(bh1, sb + O_B + (uint32_t)(wn + 16 + r7 + rB8) * 128 + swB);
                mma_hf(c[0][0], ah0, bh0[0], bh0[1]);
                mma_hf(c[0][1], ah0, bh0[2], bh0[3]);
                mma_hf(c[0][2], ah0, bh1[0], bh1[1]);
                mma_hf(c[0][3], ah0, bh1[2], bh1[3]);
                mma_hf(c[1][0], ah1, bh0[0], bh0[1]);
                mma_hf(c[1][1], ah1, bh0[2], bh0[3]);
                mma_hf(c[1][2], ah1, bh1[0], bh1[1]);
                mma_hf(c[1][3], ah1, bh1[2], bh1[3]);
            }
        }

        // ---- epilogue: z' = relu(0.9 z + 0.1 (Wz + Vx)) ----
        __half* __restrict__ zn = g_zh[cur ^ 1];
        float d2 = 0.0f, n2 = 0.0f;
#pragma unroll
        for (int f = 0; f < 2; f++)
#pragma unroll
            for (int g = 0; g < 4; g++)
#pragma unroll
                for (int h = 0; h < 2; h++) {
                    const int i = i0 + wm + f * 16 + h * 8 + (l >> 2);
                    const int j = j0 + wn + g * 8 + (l & 3) * 2;
                    const float2 vx = *(const float2*)&g_Vx[i * BB + j];
#pragma unroll
                    for (int p = 0; p < 2; p++) {
                        const float zv = zr[f][g][h][p];
                        const float cv = c[f][g][h * 2 + p];
                        float v = 0.9f * zv + 0.1f * (cv + (p ? vx.y : vx.x));
                        float r = v > 0.0f ? v : 0.0f;
                        zr[f][g][h][p] = r;
                        zn[(j + p) * NN + i] = __float2half_rn(r);
                        const float dd = r - zv;
                        d2 += dd * dd;
                        n2 += zv * zv;
                    }
                }

        // W prefetch for NEXT iteration — overlaps norm reduction + barrier
        A_LOAD(0, 0); A_LOAD(1, KC); A_LOAD(2, 2 * KC); CP_COMMIT();

#pragma unroll
        for (int off = 16; off; off >>= 1) {
            d2 += __shfl_xor_sync(0xffffffffu, d2, off);
            n2 += __shfl_xor_sync(0xffffffffu, n2, off);
        }
        if (l == 0) { sredD[warp] = d2; sredN[warp] = n2; }
        __syncthreads();
        const int nb = it % 3;
        if (tid == 0) {
            double Dd = 0.0, Nd = 0.0;
#pragma unroll
            for (int w = 0; w < 8; w++) { Dd += (double)sredD[w]; Nd += (double)sredN[w]; }
            atomicAdd(&g_nd[nb][0], Dd);
            atomicAdd(&g_nd[nb][1], Nd);
        }

        grid_barrier(gen);

        const double Dt = *(volatile double*)&g_nd[nb][0];
        const double Nt = *(volatile double*)&g_nd[nb][1];
        const double err = sqrt(Dt) / (sqrt(Nt) + 1e-12);
        if (blockIdx.x == 0 && tid == 0) {
            const int rb = (it + 2) % 3;
            *(volatile double*)&g_nd[rb][0] = 0.0;
            *(volatile double*)&g_nd[rb][1] = 0.0;
            __threadfence();
        }
        cur ^= 1;
        if (it >= MAXIT || err < 1e-4) { CP_WAIT(0); __syncthreads(); break; }
    }
#undef A_LOAD
#undef B_LOAD

    // write final z (register-resident) to out[i][j]
#pragma unroll
    for (int f = 0; f < 2; f++)
#pragma unroll
        for (int g = 0; g < 4; g++)
#pragma unroll
            for (int h = 0; h < 2; h++) {
                const int i = i0 + wm + f * 16 + h * 8 + (l >> 2);
                const int j = j0 + wn + g * 8 + (l & 3) * 2;
                float2 v;
                v.x = zr[f][g][h][0];
                v.y = zr[f][g][h][1];
                *(float2*)&out[i * BB + j] = v;
            }
}

extern "C" void kernel_launch(void* const* d_in, const int* in_sizes, int n_in,
                              void* d_out, int out_size) {
    const float* A     = (const float*)d_in[0];
    const float* S     = (const float*)d_in[1];
    const float* m_raw = (const float*)d_in[2];
    const float* U     = (const float*)d_in[3];
    const float* b     = (const float*)d_in[4];
    const float* x     = (const float*)d_in[5];
    float* out = (float*)d_out;

    cudaFuncSetAttribute(solve_kernel, cudaFuncAttributeMaxDynamicSharedMemorySize, DYN_SMEM);
    cudaFuncSetAttribute(build_w_mma_kernel, cudaFuncAttributeMaxDynamicSharedMemorySize, WDYN);

    init_kernel<<<(BB * NN + 255) / 256, 256>>>();
    dim3 gt(NN / 32, NN / 32);
    split_at_kernel<<<gt, 256>>>(A);
    dim3 gw(NN / 128, NN / 128);
    build_w_mma_kernel<<<gw, 256, WDYN>>>(S, m_raw);
    dim3 gv(NN / TMW, BB / TMW);
    build_vx_kernel<<<gv, 256>>>(U, b, x);
    solve_kernel<<<SB, 256, DYN_SMEM>>>(out);
}

// round 10
// speedup vs baseline: 1.4078x; 1.4078x over previous
#include <cuda_runtime.h>
#include <cuda_fp16.h>
#include <math.h>
#include <stdint.h>

#define NN 2048
#define BB 256
#define DD 512
#define MAXIT 300

// ---- solve: 32 m-tiles x 4 n-tiles = 128 CTAs, half of W smem-resident ----
#define SB 128
#define KC 64
#define NSTG 4
#define RES_CH 16                 // resident k-chunks: k < 1024
#define RESB (RES_CH*64*128)      // 128KB resident W
#define A_ST (64*128)             // 8KB
#define STGB (2*A_ST)             // ring stage: A + B
#define DYN_SMEM (RESB + NSTG*STGB + 128)
#define NKC (NN/KC)               // 32

// ---- build_w tiling --------------------------------------------------------
#define WNSTG 3
#define WMAT (128*128)
#define WSTG (2*WMAT)
#define WDYN (WNSTG*WSTG + 128)

__device__ __half  g_Wh[NN*NN];      // 8MB fp16 W
__device__ __half  g_Ath[NN*NN];     // 8MB fp16 A^T
__device__ float   g_Vx[NN*BB];      // [i][j]
__device__ __half  g_zh[2][BB*NN];   // fp16 z, [j][k], ping-pong
__device__ double  g_nd[3][2];
__device__ unsigned g_arrive, g_release;

__device__ __forceinline__ uint32_t smem_u32(const void* p) {
    uint32_t a;
    asm("{ .reg .u64 t; cvta.to.shared.u64 t, %1; cvt.u32.u64 %0, t; }" : "=r"(a) : "l"(p));
    return a;
}
__device__ __forceinline__ void cp16(uint32_t dst, const void* src) {
    asm volatile("cp.async.cg.shared.global [%0], [%1], 16;" :: "r"(dst), "l"(src) : "memory");
}
#define CP_COMMIT() asm volatile("cp.async.commit_group;" ::: "memory")
#define CP_WAIT(n)  asm volatile("cp.async.wait_group %0;" :: "n"(n) : "memory")
__device__ __forceinline__ void ldsm4(uint32_t* r, uint32_t a) {
    asm volatile("ldmatrix.sync.aligned.m8n8.x4.shared.b16 {%0,%1,%2,%3}, [%4];"
                 : "=r"(r[0]), "=r"(r[1]), "=r"(r[2]), "=r"(r[3]) : "r"(a));
}
__device__ __forceinline__ void mma_hf(float* c, const uint32_t* a, uint32_t b0, uint32_t b1) {
    asm volatile("mma.sync.aligned.m16n8k16.row.col.f32.f16.f16.f32 "
                 "{%0,%1,%2,%3}, {%4,%5,%6,%7}, {%8,%9}, {%0,%1,%2,%3};"
                 : "+f"(c[0]), "+f"(c[1]), "+f"(c[2]), "+f"(c[3])
                 : "r"(a[0]), "r"(a[1]), "r"(a[2]), "r"(a[3]), "r"(b0), "r"(b1));
}

__global__ void init_kernel() {
    int idx = blockIdx.x * blockDim.x + threadIdx.x;
    if (idx < BB * NN) g_zh[0][idx] = __float2half(0.0f);
    if (idx == 0) {
        for (int i = 0; i < 3; i++) { g_nd[i][0] = 0.0; g_nd[i][1] = 0.0; }
        g_arrive = 0u; g_release = 0u;
    }
}

// At[i][k] = A[k][i] in fp16
__global__ void __launch_bounds__(256) split_at_kernel(const float* __restrict__ A) {
    __shared__ float t[32][33];
    const int i0 = blockIdx.x * 32, k0 = blockIdx.y * 32;
    const int lx = threadIdx.x & 31, ly = threadIdx.x >> 5;
#pragma unroll
    for (int r = 0; r < 32; r += 8)
        t[ly + r][lx] = A[(long)(k0 + ly + r) * NN + i0 + lx];
    __syncthreads();
#pragma unroll
    for (int r = 0; r < 32; r += 8)
        g_Ath[(long)(i0 + ly + r) * NN + k0 + lx] = __float2half_rn(t[lx][ly + r]);
}

// W = (1-m)I - At At^T + S - S^T  (fp16 mma), output fp16
__global__ void __launch_bounds__(256, 1) build_w_mma_kernel(const float* __restrict__ S,
                                                             const float* __restrict__ m_raw) {
    extern __shared__ __align__(16) char dsm[];
    const uint32_t sbase = (smem_u32(dsm) + 127u) & ~127u;
    const int tid = threadIdx.x, l = tid & 31, warp = tid >> 5;
    const int i0 = blockIdx.x * 128, j0 = blockIdx.y * 128;
    const int wm = (warp >> 2) * 64, wn = (warp & 3) * 32;
    const int r7 = l & 7;
    const int rowA = wm + r7 + ((l >> 3) & 1) * 8;
    const int kgA = (l >> 4) & 1;
    const int rowBb = wn + r7 + ((l >> 4) & 1) * 8;
    const int kgB = (l >> 3) & 1;

    float c[4][4][4];
#pragma unroll
    for (int f = 0; f < 4; f++)
#pragma unroll
        for (int g = 0; g < 4; g++)
#pragma unroll
            for (int q = 0; q < 4; q++) c[f][g][q] = 0.0f;

#define W_LOAD(stg, k0v) do {                                                 \
    const uint32_t sb_ = sbase + (stg) * WSTG;                                \
    _Pragma("unroll")                                                         \
    for (int rep = 0; rep < 4; rep++) {                                       \
        const int idx_ = tid + rep * 256;                                     \
        const int r_ = idx_ >> 3, c_ = idx_ & 7;                              \
        const uint32_t d_ = (uint32_t)r_ * 128 + ((uint32_t)(c_ ^ (r_ & 7)) << 4); \
        cp16(sb_ + 0*WMAT + d_, g_Ath + (long)(i0 + r_) * NN + (k0v) + c_ * 8); \
        cp16(sb_ + 1*WMAT + d_, g_Ath + (long)(j0 + r_) * NN + (k0v) + c_ * 8); \
    } } while (0)

#pragma unroll
    for (int s = 0; s < WNSTG - 1; s++) { W_LOAD(s, s * KC); CP_COMMIT(); }

    for (int kc = 0; kc < NKC; kc++) {
        CP_WAIT(WNSTG - 2);
        __syncthreads();
        if (kc + WNSTG - 1 < NKC) W_LOAD((kc + WNSTG - 1) % WNSTG, (kc + WNSTG - 1) * KC);
        CP_COMMIT();
        const uint32_t sb = sbase + (kc % WNSTG) * WSTG;
#pragma unroll
        for (int s4 = 0; s4 < 4; s4++) {
            const int kg0 = s4 * 2;
            const uint32_t swA = (uint32_t)((kg0 + kgA) ^ r7) << 4;
            const uint32_t swB = (uint32_t)((kg0 + kgB) ^ r7) << 4;
            uint32_t ah[4][4], bh[2][4];
#pragma unroll
            for (int f = 0; f < 4; f++)
                ldsm4(ah[f], sb + 0*WMAT + (uint32_t)(rowA + f * 16) * 128 + swA);
#pragma unroll
            for (int g2 = 0; g2 < 2; g2++)
                ldsm4(bh[g2], sb + 1*WMAT + (uint32_t)(rowBb + g2 * 16) * 128 + swB);
#pragma unroll
            for (int f = 0; f < 4; f++)
#pragma unroll
                for (int g2 = 0; g2 < 2; g2++) {
                    mma_hf(c[f][g2*2+0], ah[f], bh[g2][0], bh[g2][1]);
                    mma_hf(c[f][g2*2+1], ah[f], bh[g2][2], bh[g2][3]);
                }
        }
    }
#undef W_LOAD

    const float m = log1pf(expf(m_raw[0]));
    const float omm = 1.0f - m;
#pragma unroll
    for (int f = 0; f < 4; f++)
#pragma unroll
        for (int g = 0; g < 4; g++)
#pragma unroll
            for (int h = 0; h < 2; h++) {
                const int i = i0 + wm + f * 16 + h * 8 + (l >> 2);
                const int j = j0 + wn + g * 8 + (l & 3) * 2;
                float2 sij = *(const float2*)&S[(long)i * NN + j];
                float w0 = -c[f][g][h*2+0] + sij.x - S[(long)j * NN + i];
                float w1 = -c[f][g][h*2+1] + sij.y - S[(long)(j + 1) * NN + i];
                if (i == j) w0 += omm;
                if (i == j + 1) w1 += omm;
                *(__half2*)&g_Wh[(long)i * NN + j] = __floats2half2_rn(w0, w1);
            }
}

#define TMW 64
#define KTW 16
#define PADW 68
__global__ void __launch_bounds__(256) build_vx_kernel(const float* __restrict__ U,
                                                       const float* __restrict__ b,
                                                       const float* __restrict__ x) {
    __shared__ __align__(16) float Us[KTW][PADW];
    __shared__ __align__(16) float Xs[KTW][PADW];
    const int i0 = blockIdx.x * TMW, j0 = blockIdx.y * TMW;
    const int tx = threadIdx.x & 15, ty = threadIdx.x >> 4;
    float acc[4][4];
#pragma unroll
    for (int a = 0; a < 4; a++)
#pragma unroll
        for (int cc = 0; cc < 4; cc++) acc[a][cc] = 0.0f;
    for (int k0 = 0; k0 < DD; k0 += KTW) {
#pragma unroll
        for (int t = threadIdx.x; t < KTW * TMW; t += 256) {
            int rr = t >> 4, cc = t & 15;
            Us[cc][rr] = U[(i0 + rr) * DD + k0 + cc];
            Xs[cc][rr] = x[(j0 + rr) * DD + k0 + cc];
        }
        __syncthreads();
#pragma unroll
        for (int k = 0; k < KTW; k++) {
            float4 av = *(const float4*)&Us[k][ty * 4];
            float4 bv = *(const float4*)&Xs[k][tx * 4];
            float am[4] = {av.x, av.y, av.z, av.w};
            float bn[4] = {bv.x, bv.y, bv.z, bv.w};
#pragma unroll
            for (int mi = 0; mi < 4; mi++)
#pragma unroll
                for (int ni = 0; ni < 4; ni++) acc[mi][ni] += am[mi] * bn[ni];
        }
        __syncthreads();
    }
#pragma unroll
    for (int mi = 0; mi < 4; mi++) {
        const int i = i0 + ty * 4 + mi;
        const float bi = b[i];
#pragma unroll
        for (int ni = 0; ni < 4; ni++)
            g_Vx[i * BB + j0 + tx * 4 + ni] = acc[mi][ni] + bi;
    }
}

__device__ __forceinline__ void grid_barrier(unsigned& gen) {
    __syncthreads();
    if (threadIdx.x == 0) {
        gen++;
        __threadfence();
        unsigned prev = atomicAdd(&g_arrive, 1u);
        if (prev == SB - 1) {
            atomicExch(&g_arrive, 0u);
            __threadfence();
            atomicExch(&g_release, gen);
        } else {
            while (*(volatile unsigned*)&g_release < gen) { }
            __threadfence();
        }
    }
    __syncthreads();
}

// ---------------- persistent fp16 solver, half-W resident in SMEM -----------
__global__ void __launch_bounds__(256, 1) solve_kernel(float* __restrict__ out) {
    extern __shared__ __align__(16) char dsm[];
    const uint32_t sbase = (smem_u32(dsm) + 127u) & ~127u;
    __shared__ float sredD[8], sredN[8];

    const int tid = threadIdx.x, l = tid & 31, warp = tid >> 5;
    const int i0 = (blockIdx.x >> 2) * 64, j0 = (blockIdx.x & 3) * 64;
    const int wm = (warp >> 2) * 32, wn = (warp & 3) * 16;
    const int r7 = l & 7;
    const int rowA0 = wm + r7 + ((l >> 3) & 1) * 8;
    const int kgA = (l >> 4) & 1;
    const int rowB = wn + r7 + ((l >> 4) & 1) * 8;
    const int kgB = (l >> 3) & 1;

    // ---- load resident W half: rows i0..i0+63, k in [0, 1024) ----
#pragma unroll
    for (int rep = 0; rep < 32; rep++) {
        const int idx = tid + rep * 256;          // 0..8191
        const int ch = idx >> 9;                  // k-chunk 0..15
        const int rem = idx & 511;
        const int r_ = rem >> 3, c_ = rem & 7;
        cp16(sbase + (uint32_t)ch * (uint32_t)A_ST + (uint32_t)r_ * 128 +
                 ((uint32_t)(c_ ^ (r_ & 7)) << 4),
             g_Wh + (long)(i0 + r_) * NN + ch * KC + c_ * 8);
    }
    CP_COMMIT(); CP_WAIT(0); __syncthreads();

    const uint32_t O_RING = sbase + RESB;

    // fp32 state in registers
    float zr[2][2][2][2], vx[2][2][2][2];
#pragma unroll
    for (int f = 0; f < 2; f++)
#pragma unroll
        for (int g = 0; g < 2; g++)
#pragma unroll
            for (int h = 0; h < 2; h++) {
                const int i = i0 + wm + f * 16 + h * 8 + (l >> 2);
                const int j = j0 + wn + g * 8 + (l & 3) * 2;
                float2 v = *(const float2*)&g_Vx[i * BB + j];
                vx[f][g][h][0] = v.x; vx[f][g][h][1] = v.y;
                zr[f][g][h][0] = 0.0f; zr[f][g][h][1] = 0.0f;
            }

    // loader geometry: 512 cp16 per stage-matrix -> 2 per thread
    const int ld_r0 = tid >> 3, ld_c = tid & 7;
    const uint32_t ld_d0 = (uint32_t)ld_r0 * 128 + ((uint32_t)(ld_c ^ (ld_r0 & 7)) << 4);
    const int ld_r1 = ld_r0 + 32;
    const uint32_t ld_d1 = (uint32_t)ld_r1 * 128 + ((uint32_t)(ld_c ^ (ld_r1 & 7)) << 4);

#define STAGE_LOAD(kcn, zp) do {                                              \
    const int kn_ = (kcn);                                                    \
    const uint32_t st_ = O_RING + (uint32_t)(kn_ & 3) * STGB;                 \
    const int k0_ = kn_ * KC;                                                 \
    if (kn_ >= RES_CH) {                                                      \
        cp16(st_ + ld_d0, g_Wh + (long)(i0 + ld_r0) * NN + k0_ + ld_c * 8);   \
        cp16(st_ + ld_d1, g_Wh + (long)(i0 + ld_r1) * NN + k0_ + ld_c * 8);   \
    }                                                                         \
    cp16(st_ + A_ST + ld_d0, (zp) + (long)(j0 + ld_r0) * NN + k0_ + ld_c * 8);\
    cp16(st_ + A_ST + ld_d1, (zp) + (long)(j0 + ld_r1) * NN + k0_ + ld_c * 8);\
    } while (0)

    unsigned gen = 0;
    int cur = 0, it = 0;

    while (1) {
        it++;
        const __half* __restrict__ zp = g_zh[cur];
        float c[2][2][4];
#pragma unroll
        for (int f = 0; f < 2; f++)
#pragma unroll
            for (int g = 0; g < 2; g++)
#pragma unroll
                for (int q = 0; q < 4; q++) c[f][g][q] = 0.0f;

#pragma unroll
        for (int s = 0; s < NSTG - 1; s++) { STAGE_LOAD(s, zp); CP_COMMIT(); }

        for (int kc = 0; kc < NKC; kc++) {
            CP_WAIT(NSTG - 2);
            __syncthreads();
            if (kc + NSTG - 1 < NKC) STAGE_LOAD(kc + NSTG - 1, zp);
            CP_COMMIT();

            const uint32_t abase = (kc < RES_CH)
                ? sbase + (uint32_t)kc * (uint32_t)A_ST
                : O_RING + (uint32_t)(kc & 3) * STGB;
            const uint32_t bbase = O_RING + (uint32_t)(kc & 3) * STGB + A_ST;
#pragma unroll
            for (int s4 = 0; s4 < 4; s4++) {
                const int kg0 = s4 * 2;
                const uint32_t swA = (uint32_t)((kg0 + kgA) ^ r7) << 4;
                const uint32_t swB = (uint32_t)((kg0 + kgB) ^ r7) << 4;
                uint32_t ah0[4], ah1[4], bh[4];
                ldsm4(ah0, abase + (uint32_t)rowA0 * 128 + swA);
                ldsm4(ah1, abase + (uint32_t)(rowA0 + 16) * 128 + swA);
                ldsm4(bh, bbase + (uint32_t)rowB * 128 + swB);
                mma_hf(c[0][0], ah0, bh[0], bh[1]);
                mma_hf(c[0][1], ah0, bh[2], bh[3]);
                mma_hf(c[1][0], ah1, bh[0], bh[1]);
                mma_hf(c[1][1], ah1, bh[2], bh[3]);
            }
        }

        // ---- epilogue: z' = relu(0.9 z + 0.1 (Wz + Vx)) ----
        __half* __restrict__ zn = g_zh[cur ^ 1];
        float d2 = 0.0f, n2 = 0.0f;
#pragma unroll
        for (int f = 0; f < 2; f++)
#pragma unroll
            for (int g = 0; g < 2; g++)
#pragma unroll
                for (int h = 0; h < 2; h++) {
                    const int i = i0 + wm + f * 16 + h * 8 + (l >> 2);
                    const int j = j0 + wn + g * 8 + (l & 3) * 2;
#pragma unroll
                    for (int p = 0; p < 2; p++) {
                        const float zv = zr[f][g][h][p];
                        float v = 0.9f * zv + 0.1f * (c[f][g][h*2+p] + vx[f][g][h][p]);
                        float r = v > 0.0f ? v : 0.0f;
                        zr[f][g][h][p] = r;
                        zn[(j + p) * NN + i] = __float2half_rn(r);
                        const float dd = r - zv;
                        d2 += dd * dd;
                        n2 += zv * zv;
                    }
                }
#pragma unroll
        for (int off = 16; off; off >>= 1) {
            d2 += __shfl_xor_sync(0xffffffffu, d2, off);
            n2 += __shfl_xor_sync(0xffffffffu, n2, off);
        }
        if (l == 0) { sredD[warp] = d2; sredN[warp] = n2; }
        __syncthreads();
        const int nb = it % 3;
        if (tid == 0) {
            double Dd = 0.0, Nd = 0.0;
#pragma unroll
            for (int w = 0; w < 8; w++) { Dd += (double)sredD[w]; Nd += (double)sredN[w]; }
            atomicAdd(&g_nd[nb][0], Dd);
            atomicAdd(&g_nd[nb][1], Nd);
        }

        grid_barrier(gen);

        const double Dt = *(volatile double*)&g_nd[nb][0];
        const double Nt = *(volatile double*)&g_nd[nb][1];
        const double err = sqrt(Dt) / (sqrt(Nt) + 1e-12);
        if (blockIdx.x == 0 && tid == 0) {
            const int rb = (it + 2) % 3;
            *(volatile double*)&g_nd[rb][0] = 0.0;
            *(volatile double*)&g_nd[rb][1] = 0.0;
            __threadfence();
        }
        cur ^= 1;
        if (it >= MAXIT || err < 1e-4) break;
    }
#undef STAGE_LOAD

    // write final z (register-resident) to out[i][j]
#pragma unroll
    for (int f = 0; f < 2; f++)
#pragma unroll
        for (int g = 0; g < 2; g++)
#pragma unroll
            for (int h = 0; h < 2; h++) {
                const int i = i0 + wm + f * 16 + h * 8 + (l >> 2);
                const int j = j0 + wn + g * 8 + (l & 3) * 2;
                float2 v;
                v.x = zr[f][g][h][0];
                v.y = zr[f][g][h][1];
                *(float2*)&out[i * BB + j] = v;
            }
}

extern "C" void kernel_launch(void* const* d_in, const int* in_sizes, int n_in,
                              void* d_out, int out_size) {
    const float* A     = (const float*)d_in[0];
    const float* S     = (const float*)d_in[1];
    const float* m_raw = (const float*)d_in[2];
    const float* U     = (const float*)d_in[3];
    const float* b     = (const float*)d_in[4];
    const float* x     = (const float*)d_in[5];
    float* out = (float*)d_out;

    cudaFuncSetAttribute(solve_kernel, cudaFuncAttributeMaxDynamicSharedMemorySize, DYN_SMEM);
    cudaFuncSetAttribute(build_w_mma_kernel, cudaFuncAttributeMaxDynamicSharedMemorySize, WDYN);

    init_kernel<<<(BB * NN + 255) / 256, 256>>>();
    dim3 gt(NN / 32, NN / 32);
    split_at_kernel<<<gt, 256>>>(A);
    dim3 gw(NN / 128, NN / 128);
    build_w_mma_kernel<<<gw, 256, WDYN>>>(S, m_raw);
    dim3 gv(NN / TMW, BB / TMW);
    build_vx_kernel<<<gv, 256>>>(U, b, x);
    solve_kernel<<<SB, 256, DYN_SMEM>>>(out);
}

// round 11
// speedup vs baseline: 1.4387x; 1.0220x over previous
#include <cuda_runtime.h>
#include <cuda_fp16.h>
#include <math.h>
#include <stdint.h>

#define NN 2048
#define BB 256
#define DD 512
#define MAXIT 300

// ---- solve: 32 m x 4 n = 128 CTAs; W k<1024 smem-resident; KC=128 ----------
#define SB 128
#define KC 128
#define NKC 16                    // 2048/128
#define NSTG 3
#define SUBB 8192                 // 64 rows x 128B sub-tile
#define RES_SUB 16                // resident 64k sub-chunks (k<1024)
#define RESB (RES_SUB*SUBB)       // 128KB
#define STGB (4*SUBB)             // ring stage: A(2 subs)+B(2 subs) = 32KB
#define DYN_SMEM (RESB + NSTG*STGB + 128)

// ---- build_w tiling --------------------------------------------------------
#define WNSTG 3
#define WMAT (128*128)
#define WSTG (2*WMAT)
#define WDYN (WNSTG*WSTG + 128)
#define WKC 64
#define WNKC (NN/WKC)

__device__ __half  g_Wh[NN*NN];      // 8MB fp16 W
__device__ __half  g_Ath[NN*NN];     // 8MB fp16 A^T
__device__ float   g_Vx[NN*BB];      // [i][j]
__device__ __half  g_zh[2][BB*NN];   // fp16 z, [j][k], ping-pong
__device__ double  g_nd[3][2];
__device__ unsigned g_arrive, g_release;

__device__ __forceinline__ uint32_t smem_u32(const void* p) {
    uint32_t a;
    asm("{ .reg .u64 t; cvta.to.shared.u64 t, %1; cvt.u32.u64 %0, t; }" : "=r"(a) : "l"(p));
    return a;
}
__device__ __forceinline__ void cp16(uint32_t dst, const void* src) {
    asm volatile("cp.async.cg.shared.global [%0], [%1], 16;" :: "r"(dst), "l"(src) : "memory");
}
#define CP_COMMIT() asm volatile("cp.async.commit_group;" ::: "memory")
#define CP_WAIT(n)  asm volatile("cp.async.wait_group %0;" :: "n"(n) : "memory")
__device__ __forceinline__ void ldsm4(uint32_t* r, uint32_t a) {
    asm volatile("ldmatrix.sync.aligned.m8n8.x4.shared.b16 {%0,%1,%2,%3}, [%4];"
                 : "=r"(r[0]), "=r"(r[1]), "=r"(r[2]), "=r"(r[3]) : "r"(a));
}
__device__ __forceinline__ void mma_hf(float* c, const uint32_t* a, uint32_t b0, uint32_t b1) {
    asm volatile("mma.sync.aligned.m16n8k16.row.col.f32.f16.f16.f32 "
                 "{%0,%1,%2,%3}, {%4,%5,%6,%7}, {%8,%9}, {%0,%1,%2,%3};"
                 : "+f"(c[0]), "+f"(c[1]), "+f"(c[2]), "+f"(c[3])
                 : "r"(a[0]), "r"(a[1]), "r"(a[2]), "r"(a[3]), "r"(b0), "r"(b1));
}

// tiny init: scalar state only (z buffers are written before ever read)
__global__ void init_small() {
    if (threadIdx.x == 0) {
        for (int i = 0; i < 3; i++) { g_nd[i][0] = 0.0; g_nd[i][1] = 0.0; }
        g_arrive = 0u; g_release = 0u;
    }
}

// At[i][k] = A[k][i] in fp16
__global__ void __launch_bounds__(256) split_at_kernel(const float* __restrict__ A) {
    __shared__ float t[32][33];
    const int i0 = blockIdx.x * 32, k0 = blockIdx.y * 32;
    const int lx = threadIdx.x & 31, ly = threadIdx.x >> 5;
#pragma unroll
    for (int r = 0; r < 32; r += 8)
        t[ly + r][lx] = A[(long)(k0 + ly + r) * NN + i0 + lx];
    __syncthreads();
#pragma unroll
    for (int r = 0; r < 32; r += 8)
        g_Ath[(long)(i0 + ly + r) * NN + k0 + lx] = __float2half_rn(t[lx][ly + r]);
}

// W = (1-m)I - At At^T + S - S^T  (fp16 mma), output fp16
__global__ void __launch_bounds__(256, 1) build_w_mma_kernel(const float* __restrict__ S,
                                                             const float* __restrict__ m_raw) {
    extern __shared__ __align__(16) char dsm[];
    const uint32_t sbase = (smem_u32(dsm) + 127u) & ~127u;
    const int tid = threadIdx.x, l = tid & 31, warp = tid >> 5;
    const int i0 = blockIdx.x * 128, j0 = blockIdx.y * 128;
    const int wm = (warp >> 2) * 64, wn = (warp & 3) * 32;
    const int r7 = l & 7;
    const int rowA = wm + r7 + ((l >> 3) & 1) * 8;
    const int kgA = (l >> 4) & 1;
    const int rowBb = wn + r7 + ((l >> 4) & 1) * 8;
    const int kgB = (l >> 3) & 1;

    float c[4][4][4];
#pragma unroll
    for (int f = 0; f < 4; f++)
#pragma unroll
        for (int g = 0; g < 4; g++)
#pragma unroll
            for (int q = 0; q < 4; q++) c[f][g][q] = 0.0f;

#define W_LOAD(stg, k0v) do {                                                 \
    const uint32_t sb_ = sbase + (stg) * WSTG;                                \
    _Pragma("unroll")                                                         \
    for (int rep = 0; rep < 4; rep++) {                                       \
        const int idx_ = tid + rep * 256;                                     \
        const int r_ = idx_ >> 3, c_ = idx_ & 7;                              \
        const uint32_t d_ = (uint32_t)r_ * 128 + ((uint32_t)(c_ ^ (r_ & 7)) << 4); \
        cp16(sb_ + 0*WMAT + d_, g_Ath + (long)(i0 + r_) * NN + (k0v) + c_ * 8); \
        cp16(sb_ + 1*WMAT + d_, g_Ath + (long)(j0 + r_) * NN + (k0v) + c_ * 8); \
    } } while (0)

#pragma unroll
    for (int s = 0; s < WNSTG - 1; s++) { W_LOAD(s, s * WKC); CP_COMMIT(); }

    for (int kc = 0; kc < WNKC; kc++) {
        CP_WAIT(WNSTG - 2);
        __syncthreads();
        if (kc + WNSTG - 1 < WNKC) W_LOAD((kc + WNSTG - 1) % WNSTG, (kc + WNSTG - 1) * WKC);
        CP_COMMIT();
        const uint32_t sb = sbase + (kc % WNSTG) * WSTG;
#pragma unroll
        for (int s4 = 0; s4 < 4; s4++) {
            const int kg0 = s4 * 2;
            const uint32_t swA = (uint32_t)((kg0 + kgA) ^ r7) << 4;
            const uint32_t swB = (uint32_t)((kg0 + kgB) ^ r7) << 4;
            uint32_t ah[4][4], bh[2][4];
#pragma unroll
            for (int f = 0; f < 4; f++)
                ldsm4(ah[f], sb + 0*WMAT + (uint32_t)(rowA + f * 16) * 128 + swA);
#pragma unroll
            for (int g2 = 0; g2 < 2; g2++)
                ldsm4(bh[g2], sb + 1*WMAT + (uint32_t)(rowBb + g2 * 16) * 128 + swB);
#pragma unroll
            for (int f = 0; f < 4; f++)
#pragma unroll
                for (int g2 = 0; g2 < 2; g2++) {
                    mma_hf(c[f][g2*2+0], ah[f], bh[g2][0], bh[g2][1]);
                    mma_hf(c[f][g2*2+1], ah[f], bh[g2][2], bh[g2][3]);
                }
        }
    }
#undef W_LOAD

    const float m = log1pf(expf(m_raw[0]));
    const float omm = 1.0f - m;
#pragma unroll
    for (int f = 0; f < 4; f++)
#pragma unroll
        for (int g = 0; g < 4; g++)
#pragma unroll
            for (int h = 0; h < 2; h++) {
                const int i = i0 + wm + f * 16 + h * 8 + (l >> 2);
                const int j = j0 + wn + g * 8 + (l & 3) * 2;
                float2 sij = *(const float2*)&S[(long)i * NN + j];
                float w0 = -c[f][g][h*2+0] + sij.x - S[(long)j * NN + i];
                float w1 = -c[f][g][h*2+1] + sij.y - S[(long)(j + 1) * NN + i];
                if (i == j) w0 += omm;
                if (i == j + 1) w1 += omm;
                *(__half2*)&g_Wh[(long)i * NN + j] = __floats2half2_rn(w0, w1);
            }
}

#define TMW 64
#define KTW 16
#define PADW 68
__global__ void __launch_bounds__(256) build_vx_kernel(const float* __restrict__ U,
                                                       const float* __restrict__ b,
                                                       const float* __restrict__ x) {
    __shared__ __align__(16) float Us[KTW][PADW];
    __shared__ __align__(16) float Xs[KTW][PADW];
    const int i0 = blockIdx.x * TMW, j0 = blockIdx.y * TMW;
    const int tx = threadIdx.x & 15, ty = threadIdx.x >> 4;
    float acc[4][4];
#pragma unroll
    for (int a = 0; a < 4; a++)
#pragma unroll
        for (int cc = 0; cc < 4; cc++) acc[a][cc] = 0.0f;
    for (int k0 = 0; k0 < DD; k0 += KTW) {
#pragma unroll
        for (int t = threadIdx.x; t < KTW * TMW; t += 256) {
            int rr = t >> 4, cc = t & 15;
            Us[cc][rr] = U[(i0 + rr) * DD + k0 + cc];
            Xs[cc][rr] = x[(j0 + rr) * DD + k0 + cc];
        }
        __syncthreads();
#pragma unroll
        for (int k = 0; k < KTW; k++) {
            float4 av = *(const float4*)&Us[k][ty * 4];
            float4 bv = *(const float4*)&Xs[k][tx * 4];
            float am[4] = {av.x, av.y, av.z, av.w};
            float bn[4] = {bv.x, bv.y, bv.z, bv.w};
#pragma unroll
            for (int mi = 0; mi < 4; mi++)
#pragma unroll
                for (int ni = 0; ni < 4; ni++) acc[mi][ni] += am[mi] * bn[ni];
        }
        __syncthreads();
    }
#pragma unroll
    for (int mi = 0; mi < 4; mi++) {
        const int i = i0 + ty * 4 + mi;
        const float bi = b[i];
#pragma unroll
        for (int ni = 0; ni < 4; ni++)
            g_Vx[i * BB + j0 + tx * 4 + ni] = acc[mi][ni] + bi;
    }
}

__device__ __forceinline__ void grid_barrier(unsigned& gen) {
    __syncthreads();
    if (threadIdx.x == 0) {
        gen++;
        __threadfence();
        unsigned prev = atomicAdd(&g_arrive, 1u);
        if (prev == SB - 1) {
            atomicExch(&g_arrive, 0u);
            __threadfence();
            atomicExch(&g_release, gen);
        } else {
            while (*(volatile unsigned*)&g_release < gen) { }
            __threadfence();
        }
    }
    __syncthreads();
}

// ---------------- persistent fp16 solver, half-W resident, KC=128 -----------
__global__ void __launch_bounds__(256, 1) solve_kernel(float* __restrict__ out) {
    extern __shared__ __align__(16) char dsm[];
    const uint32_t sbase = (smem_u32(dsm) + 127u) & ~127u;
    __shared__ float sredD[8], sredN[8];

    const int tid = threadIdx.x, l = tid & 31, warp = tid >> 5;
    const int i0 = (blockIdx.x >> 2) * 64, j0 = (blockIdx.x & 3) * 64;
    const int wm = (warp >> 2) * 32, wn = (warp & 3) * 16;
    const int r7 = l & 7;
    const int rowA0 = wm + r7 + ((l >> 3) & 1) * 8;
    const int kgA = (l >> 4) & 1;
    const int rowB = wn + r7 + ((l >> 4) & 1) * 8;
    const int kgB = (l >> 3) & 1;

    // ---- resident W: rows i0..i0+63, k < 1024 (16 sub-chunks of 8KB) ----
#pragma unroll
    for (int rep = 0; rep < 32; rep++) {
        const int idx = tid + rep * 256;          // 0..8191
        const int ch = idx >> 9;                  // 64k sub-chunk 0..15
        const int rem = idx & 511;
        const int r_ = rem >> 3, c_ = rem & 7;
        cp16(sbase + (uint32_t)ch * SUBB + (uint32_t)r_ * 128 +
                 ((uint32_t)(c_ ^ (r_ & 7)) << 4),
             g_Wh + (long)(i0 + r_) * NN + ch * 64 + c_ * 8);
    }
    CP_COMMIT(); CP_WAIT(0); __syncthreads();

    const uint32_t O_RING = sbase + RESB;

    // fp32 state in registers
    float zr[2][2][2][2], vx[2][2][2][2];
#pragma unroll
    for (int f = 0; f < 2; f++)
#pragma unroll
        for (int g = 0; g < 2; g++)
#pragma unroll
            for (int h = 0; h < 2; h++) {
                const int i = i0 + wm + f * 16 + h * 8 + (l >> 2);
                const int j = j0 + wn + g * 8 + (l & 3) * 2;
                float2 v = *(const float2*)&g_Vx[i * BB + j];
                vx[f][g][h][0] = v.x; vx[f][g][h][1] = v.y;
                zr[f][g][h][0] = 0.0f; zr[f][g][h][1] = 0.0f;
            }

    // stage loader: A (stream half only) + B, 2 sub-tiles each, 32KB stage
#define STAGE_LOAD(kcn, zp) do {                                              \
    const int kn_ = (kcn);                                                    \
    const uint32_t st_ = O_RING + (uint32_t)((kn_) % NSTG) * STGB;            \
    const int k0_ = kn_ * KC;                                                 \
    _Pragma("unroll")                                                         \
    for (int rep_ = 0; rep_ < 4; rep_++) {                                    \
        const int idx_ = tid + rep_ * 256;       /* 0..1023 */                \
        const int sub_ = idx_ >> 9;                                           \
        const int rem_ = idx_ & 511;                                          \
        const int r_ = rem_ >> 3, c_ = rem_ & 7;                              \
        const uint32_t d_ = (uint32_t)sub_ * SUBB + (uint32_t)r_ * 128 +      \
                            ((uint32_t)(c_ ^ (r_ & 7)) << 4);                 \
        if (kn_ >= 8)                                                         \
            cp16(st_ + d_, g_Wh + (long)(i0 + r_) * NN + k0_ + sub_ * 64 + c_ * 8); \
        cp16(st_ + 2u * SUBB + d_,                                            \
             (zp) + (long)(j0 + r_) * NN + k0_ + sub_ * 64 + c_ * 8);         \
    } } while (0)

    unsigned gen = 0;
    int cur = 0, it = 0;

    while (1) {
        it++;
        const __half* __restrict__ zp = g_zh[cur];
        float c[2][2][4];
#pragma unroll
        for (int f = 0; f < 2; f++)
#pragma unroll
            for (int g = 0; g < 2; g++)
#pragma unroll
                for (int q = 0; q < 4; q++) c[f][g][q] = 0.0f;

        if (it > 1) {   // it==1: z0 = 0 -> Wz = 0, skip GEMM entirely
#pragma unroll
            for (int s = 0; s < NSTG - 1; s++) { STAGE_LOAD(s, zp); CP_COMMIT(); }

            for (int kc = 0; kc < NKC; kc++) {
                CP_WAIT(NSTG - 2);
                __syncthreads();
                if (kc + NSTG - 1 < NKC) STAGE_LOAD(kc + NSTG - 1, zp);
                CP_COMMIT();

                const uint32_t rst = O_RING + (uint32_t)(kc % NSTG) * STGB;
#pragma unroll
                for (int sub = 0; sub < 2; sub++) {
                    const uint32_t abase = (kc < 8)
                        ? sbase + (uint32_t)(2 * kc + sub) * SUBB
                        : rst + (uint32_t)sub * SUBB;
                    const uint32_t bbase = rst + 2u * SUBB + (uint32_t)sub * SUBB;
#pragma unroll
                    for (int s4 = 0; s4 < 4; s4++) {
                        const int kg0 = s4 * 2;
                        const uint32_t swA = (uint32_t)((kg0 + kgA) ^ r7) << 4;
                        const uint32_t swB = (uint32_t)((kg0 + kgB) ^ r7) << 4;
                        uint32_t ah0[4], ah1[4], bh[4];
                        ldsm4(ah0, abase + (uint32_t)rowA0 * 128 + swA);
                        ldsm4(ah1, abase + (uint32_t)(rowA0 + 16) * 128 + swA);
                        ldsm4(bh, bbase + (uint32_t)rowB * 128 + swB);
                        mma_hf(c[0][0], ah0, bh[0], bh[1]);
                        mma_hf(c[0][1], ah0, bh[2], bh[3]);
                        mma_hf(c[1][0], ah1, bh[0], bh[1]);
                        mma_hf(c[1][1], ah1, bh[2], bh[3]);
                    }
                }
            }
        }

        // ---- epilogue: z' = relu(0.9 z + 0.1 (Wz + Vx)) ----
        __half* __restrict__ zn = g_zh[cur ^ 1];
        float d2 = 0.0f, n2 = 0.0f;
#pragma unroll
        for (int f = 0; f < 2; f++)
#pragma unroll
            for (int g = 0; g < 2; g++)
#pragma unroll
                for (int h = 0; h < 2; h++) {
                    const int i = i0 + wm + f * 16 + h * 8 + (l >> 2);
                    const int j = j0 + wn + g * 8 + (l & 3) * 2;
#pragma unroll
                    for (int p = 0; p < 2; p++) {
                        const float zv = zr[f][g][h][p];
                        float v = 0.9f * zv + 0.1f * (c[f][g][h*2+p] + vx[f][g][h][p]);
                        float r = v > 0.0f ? v : 0.0f;
                        zr[f][g][h][p] = r;
                        zn[(j + p) * NN + i] = __float2half_rn(r);
                        const float dd = r - zv;
                        d2 += dd * dd;
                        n2 += zv * zv;
                    }
                }
#pragma unroll
        for (int off = 16; off; off >>= 1) {
            d2 += __shfl_xor_sync(0xffffffffu, d2, off);
            n2 += __shfl_xor_sync(0xffffffffu, n2, off);
        }
        if (l == 0) { sredD[warp] = d2; sredN[warp] = n2; }
        __syncthreads();
        const int nb = it % 3;
        if (tid == 0) {
            double Dd = 0.0, Nd = 0.0;
#pragma unroll
            for (int w = 0; w < 8; w++) { Dd += (double)sredD[w]; Nd += (double)sredN[w]; }
            atomicAdd(&g_nd[nb][0], Dd);
            atomicAdd(&g_nd[nb][1], Nd);
        }

        grid_barrier(gen);

        const double Dt = *(volatile double*)&g_nd[nb][0];
        const double Nt = *(volatile double*)&g_nd[nb][1];
        const double err = sqrt(Dt) / (sqrt(Nt) + 1e-12);
        if (blockIdx.x == 0 && tid == 0) {
            const int rb = (it + 2) % 3;
            *(volatile double*)&g_nd[rb][0] = 0.0;
            *(volatile double*)&g_nd[rb][1] = 0.0;
            __threadfence();
        }
        cur ^= 1;
        if (it >= MAXIT || err < 1e-4) break;
    }
#undef STAGE_LOAD

    // write final z (register-resident) to out[i][j]
#pragma unroll
    for (int f = 0; f < 2; f++)
#pragma unroll
        for (int g = 0; g < 2; g++)
#pragma unroll
            for (int h = 0; h < 2; h++) {
                const int i = i0 + wm + f * 16 + h * 8 + (l >> 2);
                const int j = j0 + wn + g * 8 + (l & 3) * 2;
                float2 v;
                v.x = zr[f][g][h][0];
                v.y = zr[f][g][h][1];
                *(float2*)&out[i * BB + j] = v;
            }
}

extern "C" void kernel_launch(void* const* d_in, const int* in_sizes, int n_in,
                              void* d_out, int out_size) {
    const float* A     = (const float*)d_in[0];
    const float* S     = (const float*)d_in[1];
    const float* m_raw = (const float*)d_in[2];
    const float* U     = (const float*)d_in[3];
    const float* b     = (const float*)d_in[4];
    const float* x     = (const float*)d_in[5];
    float* out = (float*)d_out;

    cudaFuncSetAttribute(solve_kernel, cudaFuncAttributeMaxDynamicSharedMemorySize, DYN_SMEM);
    cudaFuncSetAttribute(build_w_mma_kernel, cudaFuncAttributeMaxDynamicSharedMemorySize, WDYN);

    init_small<<<1, 32>>>();
    dim3 gt(NN / 32, NN / 32);
    split_at_kernel<<<gt, 256>>>(A);
    dim3 gw(NN / 128, NN / 128);
    build_w_mma_kernel<<<gw, 256, WDYN>>>(S, m_raw);
    dim3 gv(NN / TMW, BB / TMW);
    build_vx_kernel<<<gv, 256>>>(U, b, x);
    solve_kernel<<<SB, 256, DYN_SMEM>>>(out);
}

// round 12
// speedup vs baseline: 1.4497x; 1.0076x over previous
#include <cuda_runtime.h>
#include <cuda_fp16.h>
#include <math.h>
#include <stdint.h>

#define NN 2048
#define BB 256
#define DD 512
#define MAXIT 300

// ---- solve: 32 m x 4 n = 128 CTAs; W k<1024 smem-resident; KC=128 ----------
#define SB 128
#define KC 128
#define NKC 16
#define NSTG 3
#define SUBB 8192                 // 64 rows x 128B sub-tile
#define RES_SUB 16
#define RESB (RES_SUB*SUBB)       // 128KB
#define STGB (4*SUBB)             // stage: A(2 subs)+B(2 subs) = 32KB
#define DYN_SMEM (RESB + NSTG*STGB + 128)

// ---- build_w tiling --------------------------------------------------------
#define WNSTG 3
#define WMAT (128*128)
#define WSTG (2*WMAT)
#define WDYN (WNSTG*WSTG + 128)
#define WKC 64
#define WNKC (NN/WKC)

__device__ __half  g_Wh[NN*NN];
__device__ __half  g_Ath[NN*NN];
__device__ float   g_Vx[NN*BB];
__device__ __half  g_zh[2][BB*NN];
__device__ double  g_nd[3][2];
__device__ unsigned g_arrive, g_release;

__device__ __forceinline__ uint32_t smem_u32(const void* p) {
    uint32_t a;
    asm("{ .reg .u64 t; cvta.to.shared.u64 t, %1; cvt.u32.u64 %0, t; }" : "=r"(a) : "l"(p));
    return a;
}
__device__ __forceinline__ void cp16(uint32_t dst, const void* src) {
    asm volatile("cp.async.cg.shared.global [%0], [%1], 16;" :: "r"(dst), "l"(src) : "memory");
}
#define CP_COMMIT() asm volatile("cp.async.commit_group;" ::: "memory")
#define CP_WAIT(n)  asm volatile("cp.async.wait_group %0;" :: "n"(n) : "memory")
__device__ __forceinline__ void ldsm4(uint32_t* r, uint32_t a) {
    asm volatile("ldmatrix.sync.aligned.m8n8.x4.shared.b16 {%0,%1,%2,%3}, [%4];"
                 : "=r"(r[0]), "=r"(r[1]), "=r"(r[2]), "=r"(r[3]) : "r"(a));
}
__device__ __forceinline__ void mma_hf(float* c, const uint32_t* a, uint32_t b0, uint32_t b1) {
    asm volatile("mma.sync.aligned.m16n8k16.row.col.f32.f16.f16.f32 "
                 "{%0,%1,%2,%3}, {%4,%5,%6,%7}, {%8,%9}, {%0,%1,%2,%3};"
                 : "+f"(c[0]), "+f"(c[1]), "+f"(c[2]), "+f"(c[3])
                 : "r"(a[0]), "r"(a[1]), "r"(a[2]), "r"(a[3]), "r"(b0), "r"(b1));
}
__device__ __forceinline__ void sts_v4(uint32_t a, const float* v) {
    asm volatile("st.shared.v4.f32 [%0], {%1,%2,%3,%4};"
                 :: "r"(a), "f"(v[0]), "f"(v[1]), "f"(v[2]), "f"(v[3]) : "memory");
}
__device__ __forceinline__ void lds_v4(float* v, uint32_t a) {
    asm volatile("ld.shared.v4.f32 {%0,%1,%2,%3}, [%4];"
                 : "=f"(v[0]), "=f"(v[1]), "=f"(v[2]), "=f"(v[3]) : "r"(a));
}

__global__ void init_small() {
    if (threadIdx.x == 0) {
        for (int i = 0; i < 3; i++) { g_nd[i][0] = 0.0; g_nd[i][1] = 0.0; }
        g_arrive = 0u; g_release = 0u;
    }
}

// At[i][k] = A[k][i] in fp16
__global__ void __launch_bounds__(256) split_at_kernel(const float* __restrict__ A) {
    __shared__ float t[32][33];
    const int i0 = blockIdx.x * 32, k0 = blockIdx.y * 32;
    const int lx = threadIdx.x & 31, ly = threadIdx.x >> 5;
#pragma unroll
    for (int r = 0; r < 32; r += 8)
        t[ly + r][lx] = A[(long)(k0 + ly + r) * NN + i0 + lx];
    __syncthreads();
#pragma unroll
    for (int r = 0; r < 32; r += 8)
        g_Ath[(long)(i0 + ly + r) * NN + k0 + lx] = __float2half_rn(t[lx][ly + r]);
}

// W = (1-m)I - At At^T + S - S^T  (fp16 mma), output fp16
__global__ void __launch_bounds__(256, 1) build_w_mma_kernel(const float* __restrict__ S,
                                                             const float* __restrict__ m_raw) {
    extern __shared__ __align__(16) char dsm[];
    const uint32_t sbase = (smem_u32(dsm) + 127u) & ~127u;
    const int tid = threadIdx.x, l = tid & 31, warp = tid >> 5;
    const int i0 = blockIdx.x * 128, j0 = blockIdx.y * 128;
    const int wm = (warp >> 2) * 64, wn = (warp & 3) * 32;
    const int r7 = l & 7;
    const int rowA = wm + r7 + ((l >> 3) & 1) * 8;
    const int kgA = (l >> 4) & 1;
    const int rowBb = wn + r7 + ((l >> 4) & 1) * 8;
    const int kgB = (l >> 3) & 1;

    float c[4][4][4];
#pragma unroll
    for (int f = 0; f < 4; f++)
#pragma unroll
        for (int g = 0; g < 4; g++)
#pragma unroll
            for (int q = 0; q < 4; q++) c[f][g][q] = 0.0f;

#define W_LOAD(stg, k0v) do {                                                 \
    const uint32_t sb_ = sbase + (stg) * WSTG;                                \
    _Pragma("unroll")                                                         \
    for (int rep = 0; rep < 4; rep++) {                                       \
        const int idx_ = tid + rep * 256;                                     \
        const int r_ = idx_ >> 3, c_ = idx_ & 7;                              \
        const uint32_t d_ = (uint32_t)r_ * 128 + ((uint32_t)(c_ ^ (r_ & 7)) << 4); \
        cp16(sb_ + 0*WMAT + d_, g_Ath + (long)(i0 + r_) * NN + (k0v) + c_ * 8); \
        cp16(sb_ + 1*WMAT + d_, g_Ath + (long)(j0 + r_) * NN + (k0v) + c_ * 8); \
    } } while (0)

#pragma unroll
    for (int s = 0; s < WNSTG - 1; s++) { W_LOAD(s, s * WKC); CP_COMMIT(); }

    for (int kc = 0; kc < WNKC; kc++) {
        CP_WAIT(WNSTG - 2);
        __syncthreads();
        if (kc + WNSTG - 1 < WNKC) W_LOAD((kc + WNSTG - 1) % WNSTG, (kc + WNSTG - 1) * WKC);
        CP_COMMIT();
        const uint32_t sb = sbase + (kc % WNSTG) * WSTG;
#pragma unroll
        for (int s4 = 0; s4 < 4; s4++) {
            const int kg0 = s4 * 2;
            const uint32_t swA = (uint32_t)((kg0 + kgA) ^ r7) << 4;
            const uint32_t swB = (uint32_t)((kg0 + kgB) ^ r7) << 4;
            uint32_t ah[4][4], bh[2][4];
#pragma unroll
            for (int f = 0; f < 4; f++)
                ldsm4(ah[f], sb + 0*WMAT + (uint32_t)(rowA + f * 16) * 128 + swA);
#pragma unroll
            for (int g2 = 0; g2 < 2; g2++)
                ldsm4(bh[g2], sb + 1*WMAT + (uint32_t)(rowBb + g2 * 16) * 128 + swB);
#pragma unroll
            for (int f = 0; f < 4; f++)
#pragma unroll
                for (int g2 = 0; g2 < 2; g2++) {
                    mma_hf(c[f][g2*2+0], ah[f], bh[g2][0], bh[g2][1]);
                    mma_hf(c[f][g2*2+1], ah[f], bh[g2][2], bh[g2][3]);
                }
        }
    }
#undef W_LOAD

    const float m = log1pf(expf(m_raw[0]));
    const float omm = 1.0f - m;
#pragma unroll
    for (int f = 0; f < 4; f++)
#pragma unroll
        for (int g = 0; g < 4; g++)
#pragma unroll
            for (int h = 0; h < 2; h++) {
                const int i = i0 + wm + f * 16 + h * 8 + (l >> 2);
                const int j = j0 + wn + g * 8 + (l & 3) * 2;
                float2 sij = *(const float2*)&S[(long)i * NN + j];
                float w0 = -c[f][g][h*2+0] + sij.x - S[(long)j * NN + i];
                float w1 = -c[f][g][h*2+1] + sij.y - S[(long)(j + 1) * NN + i];
                if (i == j) w0 += omm;
                if (i == j + 1) w1 += omm;
                *(__half2*)&g_Wh[(long)i * NN + j] = __floats2half2_rn(w0, w1);
            }
}

#define TMW 64
#define KTW 16
#define PADW 68
__global__ void __launch_bounds__(256) build_vx_kernel(const float* __restrict__ U,
                                                       const float* __restrict__ b,
                                                       const float* __restrict__ x) {
    __shared__ __align__(16) float Us[KTW][PADW];
    __shared__ __align__(16) float Xs[KTW][PADW];
    const int i0 = blockIdx.x * TMW, j0 = blockIdx.y * TMW;
    const int tx = threadIdx.x & 15, ty = threadIdx.x >> 4;
    float acc[4][4];
#pragma unroll
    for (int a = 0; a < 4; a++)
#pragma unroll
        for (int cc = 0; cc < 4; cc++) acc[a][cc] = 0.0f;
    for (int k0 = 0; k0 < DD; k0 += KTW) {
#pragma unroll
        for (int t = threadIdx.x; t < KTW * TMW; t += 256) {
            int rr = t >> 4, cc = t & 15;
            Us[cc][rr] = U[(i0 + rr) * DD + k0 + cc];
            Xs[cc][rr] = x[(j0 + rr) * DD + k0 + cc];
        }
        __syncthreads();
#pragma unroll
        for (int k = 0; k < KTW; k++) {
            float4 av = *(const float4*)&Us[k][ty * 4];
            float4 bv = *(const float4*)&Xs[k][tx * 4];
            float am[4] = {av.x, av.y, av.z, av.w};
            float bn[4] = {bv.x, bv.y, bv.z, bv.w};
#pragma unroll
            for (int mi = 0; mi < 4; mi++)
#pragma unroll
                for (int ni = 0; ni < 4; ni++) acc[mi][ni] += am[mi] * bn[ni];
        }
        __syncthreads();
    }
#pragma unroll
    for (int mi = 0; mi < 4; mi++) {
        const int i = i0 + ty * 4 + mi;
        const float bi = b[i];
#pragma unroll
        for (int ni = 0; ni < 4; ni++)
            g_Vx[i * BB + j0 + tx * 4 + ni] = acc[mi][ni] + bi;
    }
}

__device__ __forceinline__ void grid_barrier(unsigned& gen) {
    __syncthreads();
    if (threadIdx.x == 0) {
        gen++;
        __threadfence();
        unsigned prev = atomicAdd(&g_arrive, 1u);
        if (prev == SB - 1) {
            atomicExch(&g_arrive, 0u);
            __threadfence();
            atomicExch(&g_release, gen);
        } else {
            while (*(volatile unsigned*)&g_release < gen) { }
            __threadfence();
        }
    }
    __syncthreads();
}

// ------ persistent fp16 solver, 32x32 warp tiles + warp k-split -------------
__global__ void __launch_bounds__(256, 1) solve_kernel(float* __restrict__ out) {
    extern __shared__ __align__(16) char dsm[];
    const uint32_t sbase = (smem_u32(dsm) + 127u) & ~127u;
    __shared__ float sredD[8], sredN[8];

    const int tid = threadIdx.x, l = tid & 31, warp = tid >> 5;
    const int i0 = (blockIdx.x >> 2) * 64, j0 = (blockIdx.x & 3) * 64;
    // warp roles: 2x2 spatial x 2-way k-split
    const int pm = (warp >> 1) & 1;    // m half (32 rows)
    const int pn = warp & 1;           // n half (32 cols)
    const int ks = warp >> 2;          // k-split (sub 0 / sub 1 of each KC step)
    const int r7 = l & 7;
    const int rA8 = ((l >> 3) & 1) * 8, selA = (l >> 4) & 1;
    const int rB8 = ((l >> 4) & 1) * 8, selB = (l >> 3) & 1;
    const int rowA0 = pm * 32 + r7 + rA8;
    const int rowB0 = pn * 32 + r7 + rB8;

    // ---- resident W: rows i0..i0+63, k < 1024 ----
#pragma unroll
    for (int rep = 0; rep < 32; rep++) {
        const int idx = tid + rep * 256;
        const int ch = idx >> 9;
        const int rem = idx & 511;
        const int r_ = rem >> 3, c_ = rem & 7;
        cp16(sbase + (uint32_t)ch * SUBB + (uint32_t)r_ * 128 +
                 ((uint32_t)(c_ ^ (r_ & 7)) << 4),
             g_Wh + (long)(i0 + r_) * NN + ch * 64 + c_ * 8);
    }
    CP_COMMIT(); CP_WAIT(0); __syncthreads();

    const uint32_t O_RING = sbase + RESB;
    const int gk = ks * 2;             // this warp's kept n8-group half

    // fp32 state: 16 elems/thread, j cols pn*32 + (gk+gi)*8
    float zr[2][2][2][2], vx[2][2][2][2];   // [f][gi][h][p]
#pragma unroll
    for (int f = 0; f < 2; f++)
#pragma unroll
        for (int gi = 0; gi < 2; gi++)
#pragma unroll
            for (int h = 0; h < 2; h++) {
                const int i = i0 + pm * 32 + f * 16 + h * 8 + (l >> 2);
                const int j = j0 + pn * 32 + (gk + gi) * 8 + (l & 3) * 2;
                float2 v = *(const float2*)&g_Vx[i * BB + j];
                vx[f][gi][h][0] = v.x; vx[f][gi][h][1] = v.y;
                zr[f][gi][h][0] = 0.0f; zr[f][gi][h][1] = 0.0f;
            }

#define STAGE_LOAD(kcn, zp) do {                                              \
    const int kn_ = (kcn);                                                    \
    const uint32_t st_ = O_RING + (uint32_t)((kn_) % NSTG) * STGB;            \
    const int k0_ = kn_ * KC;                                                 \
    _Pragma("unroll")                                                         \
    for (int rep_ = 0; rep_ < 4; rep_++) {                                    \
        const int idx_ = tid + rep_ * 256;                                    \
        const int sub_ = idx_ >> 9;                                           \
        const int rem_ = idx_ & 511;                                          \
        const int r_ = rem_ >> 3, c_ = rem_ & 7;                              \
        const uint32_t d_ = (uint32_t)sub_ * SUBB + (uint32_t)r_ * 128 +      \
                            ((uint32_t)(c_ ^ (r_ & 7)) << 4);                 \
        if (kn_ >= 8)                                                         \
            cp16(st_ + d_, g_Wh + (long)(i0 + r_) * NN + k0_ + sub_ * 64 + c_ * 8); \
        cp16(st_ + 2u * SUBB + d_,                                            \
             (zp) + (long)(j0 + r_) * NN + k0_ + sub_ * 64 + c_ * 8);         \
    } } while (0)

    unsigned gen = 0;
    int cur = 0, it = 0;

    while (1) {
        it++;
        const __half* __restrict__ zp = g_zh[cur];
        float c[2][4][4];      // [f(m16)][g(n8, 0..3 over warp's 32 cols)][q]
#pragma unroll
        for (int f = 0; f < 2; f++)
#pragma unroll
            for (int g = 0; g < 4; g++)
#pragma unroll
                for (int q = 0; q < 4; q++) c[f][g][q] = 0.0f;

        if (it > 1) {
#pragma unroll
            for (int s = 0; s < NSTG - 1; s++) { STAGE_LOAD(s, zp); CP_COMMIT(); }

            for (int kc = 0; kc < NKC; kc++) {
                CP_WAIT(NSTG - 2);
                __syncthreads();
                if (kc + NSTG - 1 < NKC) STAGE_LOAD(kc + NSTG - 1, zp);
                CP_COMMIT();

                const uint32_t rst = O_RING + (uint32_t)(kc % NSTG) * STGB;
                const uint32_t abase = (kc < 8)
                    ? sbase + (uint32_t)(2 * kc + ks) * SUBB
                    : rst + (uint32_t)ks * SUBB;
                const uint32_t bbase = rst + 2u * SUBB + (uint32_t)ks * SUBB;
#pragma unroll
                for (int s4 = 0; s4 < 4; s4++) {
                    const int kg0 = s4 * 2;
                    const uint32_t swA = (uint32_t)((kg0 + selA) ^ r7) << 4;
                    const uint32_t swB = (uint32_t)((kg0 + selB) ^ r7) << 4;
                    uint32_t ah0[4], ah1[4], bh0[4], bh1[4];
                    ldsm4(ah0, abase + (uint32_t)rowA0 * 128 + swA);
                    ldsm4(ah1, abase + (uint32_t)(rowA0 + 16) * 128 + swA);
                    ldsm4(bh0, bbase + (uint32_t)rowB0 * 128 + swB);
                    ldsm4(bh1, bbase + (uint32_t)(rowB0 + 16) * 128 + swB);
                    mma_hf(c[0][0], ah0, bh0[0], bh0[1]);
                    mma_hf(c[0][1], ah0, bh0[2], bh0[3]);
                    mma_hf(c[0][2], ah0, bh1[0], bh1[1]);
                    mma_hf(c[0][3], ah0, bh1[2], bh1[3]);
                    mma_hf(c[1][0], ah1, bh0[0], bh0[1]);
                    mma_hf(c[1][1], ah1, bh0[2], bh0[3]);
                    mma_hf(c[1][2], ah1, bh1[0], bh1[1]);
                    mma_hf(c[1][3], ah1, bh1[2], bh1[3]);
                }
            }

            // ---- k-split partial exchange (reuse ring as buffer) ----
            CP_WAIT(0);
            __syncthreads();
            const uint32_t myslot = O_RING +
                (uint32_t)((((warp & 3) * 2 + ks) * 32 + l)) * 64u;
            const uint32_t prslot = O_RING +
                (uint32_t)((((warp & 3) * 2 + (1 - ks)) * 32 + l)) * 64u;
            const int go = (1 - ks) * 2;   // half I give away
#pragma unroll
            for (int f = 0; f < 2; f++)
#pragma unroll
                for (int gi = 0; gi < 2; gi++)
                    sts_v4(myslot + (uint32_t)(f * 2 + gi) * 16u, c[f][go + gi]);
            __syncthreads();
#pragma unroll
            for (int f = 0; f < 2; f++)
#pragma unroll
                for (int gi = 0; gi < 2; gi++) {
                    float v[4];
                    lds_v4(v, prslot + (uint32_t)(f * 2 + gi) * 16u);
#pragma unroll
                    for (int q = 0; q < 4; q++) c[f][gk + gi][q] += v[q];
                }
        }

        // ---- epilogue: z' = relu(0.9 z + 0.1 (Wz + Vx)) on kept half -------
        __half* __restrict__ zn = g_zh[cur ^ 1];
        float d2 = 0.0f, n2 = 0.0f;
#pragma unroll
        for (int f = 0; f < 2; f++)
#pragma unroll
            for (int gi = 0; gi < 2; gi++)
#pragma unroll
                for (int h = 0; h < 2; h++) {
                    const int i = i0 + pm * 32 + f * 16 + h * 8 + (l >> 2);
                    const int j = j0 + pn * 32 + (gk + gi) * 8 + (l & 3) * 2;
#pragma unroll
                    for (int p = 0; p < 2; p++) {
                        const float zv = zr[f][gi][h][p];
                        float v = 0.9f * zv +
                                  0.1f * (c[f][gk + gi][h * 2 + p] + vx[f][gi][h][p]);
                        float r = v > 0.0f ? v : 0.0f;
                        zr[f][gi][h][p] = r;
                        zn[(j + p) * NN + i] = __float2half_rn(r);
                        const float dd = r - zv;
                        d2 += dd * dd;
                        n2 += zv * zv;
                    }
                }
#pragma unroll
        for (int off = 16; off; off >>= 1) {
            d2 += __shfl_xor_sync(0xffffffffu, d2, off);
            n2 += __shfl_xor_sync(0xffffffffu, n2, off);
        }
        if (l == 0) { sredD[warp] = d2; sredN[warp] = n2; }
        __syncthreads();
        const int nb = it % 3;
        if (tid == 0) {
            double Dd = 0.0, Nd = 0.0;
#pragma unroll
            for (int w = 0; w < 8; w++) { Dd += (double)sredD[w]; Nd += (double)sredN[w]; }
            atomicAdd(&g_nd[nb][0], Dd);
            atomicAdd(&g_nd[nb][1], Nd);
        }

        grid_barrier(gen);

        const double Dt = *(volatile double*)&g_nd[nb][0];
        const double Nt = *(volatile double*)&g_nd[nb][1];
        const double err = sqrt(Dt) / (sqrt(Nt) + 1e-12);
        if (blockIdx.x == 0 && tid == 0) {
            const int rb = (it + 2) % 3;
            *(volatile double*)&g_nd[rb][0] = 0.0;
            *(volatile double*)&g_nd[rb][1] = 0.0;
            __threadfence();
        }
        cur ^= 1;
        if (it >= MAXIT || err < 1e-4) break;
    }
#undef STAGE_LOAD

    // write final z (register-resident) to out[i][j]
#pragma unroll
    for (int f = 0; f < 2; f++)
#pragma unroll
        for (int gi = 0; gi < 2; gi++)
#pragma unroll
            for (int h = 0; h < 2; h++) {
                const int i = i0 + pm * 32 + f * 16 + h * 8 + (l >> 2);
                const int j = j0 + pn * 32 + (gk + gi) * 8 + (l & 3) * 2;
                float2 v;
                v.x = zr[f][gi][h][0];
                v.y = zr[f][gi][h][1];
                *(float2*)&out[i * BB + j] = v;
            }
}

extern "C" void kernel_launch(void* const* d_in, const int* in_sizes, int n_in,
                              void* d_out, int out_size) {
    const float* A     = (const float*)d_in[0];
    const float* S     = (const float*)d_in[1];
    const float* m_raw = (const float*)d_in[2];
    const float* U     = (const float*)d_in[3];
    const float* b     = (const float*)d_in[4];
    const float* x     = (const float*)d_in[5];
    float* out = (float*)d_out;

    cudaFuncSetAttribute(solve_kernel, cudaFuncAttributeMaxDynamicSharedMemorySize, DYN_SMEM);
    cudaFuncSetAttribute(build_w_mma_kernel, cudaFuncAttributeMaxDynamicSharedMemorySize, WDYN);

    init_small<<<1, 32>>>();
    dim3 gt(NN / 32, NN / 32);
    split_at_kernel<<<gt, 256>>>(A);
    dim3 gw(NN / 128, NN / 128);
    build_w_mma_kernel<<<gw, 256, WDYN>>>(S, m_raw);
    dim3 gv(NN / TMW, BB / TMW);
    build_vx_kernel<<<gv, 256>>>(U, b, x);
    solve_kernel<<<SB, 256, DYN_SMEM>>>(out);
}

// round 13
// speedup vs baseline: 1.4774x; 1.0191x over previous
#include <cuda_runtime.h>
#include <cuda_fp16.h>
#include <math.h>
#include <stdint.h>

#define NN 2048
#define BB 256
#define DD 512
#define MAXIT 300

// ---- solve: 32 m x 4 n = 128 CTAs; W k<768 smem-resident; KC=128, NSTG=4 ---
#define SB 128
#define KC 128
#define NKC 16
#define NSTG 4
#define SUBB 8192                 // 64 rows x 128B sub-tile
#define RES_SUB 12                // resident 64k sub-chunks (k<768)
#define RES_KC 6                  // kc < 6 fully resident
#define RESB (RES_SUB*SUBB)       // 96KB
#define STGB (4*SUBB)             // stage: A(2 subs)+B(2 subs) = 32KB
#define DYN_SMEM (RESB + NSTG*STGB + 128)

// ---- build_w tiling --------------------------------------------------------
#define WNSTG 3
#define WMAT (128*128)
#define WSTG (2*WMAT)
#define WDYN (WNSTG*WSTG + 128)
#define WKC 64
#define WNKC (NN/WKC)

__device__ __half  g_Wh[NN*NN];
__device__ __half  g_Ath[NN*NN];
__device__ float   g_Vx[NN*BB];
__device__ __half  g_zh[2][BB*NN];
__device__ double  g_nd[3][2];
__device__ unsigned g_arrive, g_release;

__device__ __forceinline__ uint32_t smem_u32(const void* p) {
    uint32_t a;
    asm("{ .reg .u64 t; cvta.to.shared.u64 t, %1; cvt.u32.u64 %0, t; }" : "=r"(a) : "l"(p));
    return a;
}
__device__ __forceinline__ void cp16(uint32_t dst, const void* src) {
    asm volatile("cp.async.cg.shared.global [%0], [%1], 16;" :: "r"(dst), "l"(src) : "memory");
}
#define CP_COMMIT() asm volatile("cp.async.commit_group;" ::: "memory")
#define CP_WAIT(n)  asm volatile("cp.async.wait_group %0;" :: "n"(n) : "memory")
__device__ __forceinline__ void ldsm4(uint32_t* r, uint32_t a) {
    asm volatile("ldmatrix.sync.aligned.m8n8.x4.shared.b16 {%0,%1,%2,%3}, [%4];"
                 : "=r"(r[0]), "=r"(r[1]), "=r"(r[2]), "=r"(r[3]) : "r"(a));
}
__device__ __forceinline__ void mma_hf(float* c, const uint32_t* a, uint32_t b0, uint32_t b1) {
    asm volatile("mma.sync.aligned.m16n8k16.row.col.f32.f16.f16.f32 "
                 "{%0,%1,%2,%3}, {%4,%5,%6,%7}, {%8,%9}, {%0,%1,%2,%3};"
                 : "+f"(c[0]), "+f"(c[1]), "+f"(c[2]), "+f"(c[3])
                 : "r"(a[0]), "r"(a[1]), "r"(a[2]), "r"(a[3]), "r"(b0), "r"(b1));
}
__device__ __forceinline__ void sts_v4(uint32_t a, const float* v) {
    asm volatile("st.shared.v4.f32 [%0], {%1,%2,%3,%4};"
                 :: "r"(a), "f"(v[0]), "f"(v[1]), "f"(v[2]), "f"(v[3]) : "memory");
}
__device__ __forceinline__ void lds_v4(float* v, uint32_t a) {
    asm volatile("ld.shared.v4.f32 {%0,%1,%2,%3}, [%4];"
                 : "=f"(v[0]), "=f"(v[1]), "=f"(v[2]), "=f"(v[3]) : "r"(a));
}

__global__ void init_small() {
    if (threadIdx.x == 0) {
        for (int i = 0; i < 3; i++) { g_nd[i][0] = 0.0; g_nd[i][1] = 0.0; }
        g_arrive = 0u; g_release = 0u;
    }
}

// At[i][k] = A[k][i] in fp16
__global__ void __launch_bounds__(256) split_at_kernel(const float* __restrict__ A) {
    __shared__ float t[32][33];
    const int i0 = blockIdx.x * 32, k0 = blockIdx.y * 32;
    const int lx = threadIdx.x & 31, ly = threadIdx.x >> 5;
#pragma unroll
    for (int r = 0; r < 32; r += 8)
        t[ly + r][lx] = A[(long)(k0 + ly + r) * NN + i0 + lx];
    __syncthreads();
#pragma unroll
    for (int r = 0; r < 32; r += 8)
        g_Ath[(long)(i0 + ly + r) * NN + k0 + lx] = __float2half_rn(t[lx][ly + r]);
}

// W = (1-m)I - At At^T + S - S^T  (fp16 mma), output fp16
__global__ void __launch_bounds__(256, 1) build_w_mma_kernel(const float* __restrict__ S,
                                                             const float* __restrict__ m_raw) {
    extern __shared__ __align__(16) char dsm[];
    const uint32_t sbase = (smem_u32(dsm) + 127u) & ~127u;
    const int tid = threadIdx.x, l = tid & 31, warp = tid >> 5;
    const int i0 = blockIdx.x * 128, j0 = blockIdx.y * 128;
    const int wm = (warp >> 2) * 64, wn = (warp & 3) * 32;
    const int r7 = l & 7;
    const int rowA = wm + r7 + ((l >> 3) & 1) * 8;
    const int kgA = (l >> 4) & 1;
    const int rowBb = wn + r7 + ((l >> 4) & 1) * 8;
    const int kgB = (l >> 3) & 1;

    float c[4][4][4];
#pragma unroll
    for (int f = 0; f < 4; f++)
#pragma unroll
        for (int g = 0; g < 4; g++)
#pragma unroll
            for (int q = 0; q < 4; q++) c[f][g][q] = 0.0f;

#define W_LOAD(stg, k0v) do {                                                 \
    const uint32_t sb_ = sbase + (stg) * WSTG;                                \
    _Pragma("unroll")                                                         \
    for (int rep = 0; rep < 4; rep++) {                                       \
        const int idx_ = tid + rep * 256;                                     \
        const int r_ = idx_ >> 3, c_ = idx_ & 7;                              \
        const uint32_t d_ = (uint32_t)r_ * 128 + ((uint32_t)(c_ ^ (r_ & 7)) << 4); \
        cp16(sb_ + 0*WMAT + d_, g_Ath + (long)(i0 + r_) * NN + (k0v) + c_ * 8); \
        cp16(sb_ + 1*WMAT + d_, g_Ath + (long)(j0 + r_) * NN + (k0v) + c_ * 8); \
    } } while (0)

#pragma unroll
    for (int s = 0; s < WNSTG - 1; s++) { W_LOAD(s, s * WKC); CP_COMMIT(); }

    for (int kc = 0; kc < WNKC; kc++) {
        CP_WAIT(WNSTG - 2);
        __syncthreads();
        if (kc + WNSTG - 1 < WNKC) W_LOAD((kc + WNSTG - 1) % WNSTG, (kc + WNSTG - 1) * WKC);
        CP_COMMIT();
        const uint32_t sb = sbase + (kc % WNSTG) * WSTG;
#pragma unroll
        for (int s4 = 0; s4 < 4; s4++) {
            const int kg0 = s4 * 2;
            const uint32_t swA = (uint32_t)((kg0 + kgA) ^ r7) << 4;
            const uint32_t swB = (uint32_t)((kg0 + kgB) ^ r7) << 4;
            uint32_t ah[4][4], bh[2][4];
#pragma unroll
            for (int f = 0; f < 4; f++)
                ldsm4(ah[f], sb + 0*WMAT + (uint32_t)(rowA + f * 16) * 128 + swA);
#pragma unroll
            for (int g2 = 0; g2 < 2; g2++)
                ldsm4(bh[g2], sb + 1*WMAT + (uint32_t)(rowBb + g2 * 16) * 128 + swB);
#pragma unroll
            for (int f = 0; f < 4; f++)
#pragma unroll
                for (int g2 = 0; g2 < 2; g2++) {
                    mma_hf(c[f][g2*2+0], ah[f], bh[g2][0], bh[g2][1]);
                    mma_hf(c[f][g2*2+1], ah[f], bh[g2][2], bh[g2][3]);
                }
        }
    }
#undef W_LOAD

    const float m = log1pf(expf(m_raw[0]));
    const float omm = 1.0f - m;
#pragma unroll
    for (int f = 0; f < 4; f++)
#pragma unroll
        for (int g = 0; g < 4; g++)
#pragma unroll
            for (int h = 0; h < 2; h++) {
                const int i = i0 + wm + f * 16 + h * 8 + (l >> 2);
                const int j = j0 + wn + g * 8 + (l & 3) * 2;
                float2 sij = *(const float2*)&S[(long)i * NN + j];
                float w0 = -c[f][g][h*2+0] + sij.x - S[(long)j * NN + i];
                float w1 = -c[f][g][h*2+1] + sij.y - S[(long)(j + 1) * NN + i];
                if (i == j) w0 += omm;
                if (i == j + 1) w1 += omm;
                *(__half2*)&g_Wh[(long)i * NN + j] = __floats2half2_rn(w0, w1);
            }
}

#define TMW 64
#define KTW 16
#define PADW 68
__global__ void __launch_bounds__(256) build_vx_kernel(const float* __restrict__ U,
                                                       const float* __restrict__ b,
                                                       const float* __restrict__ x) {
    __shared__ __align__(16) float Us[KTW][PADW];
    __shared__ __align__(16) float Xs[KTW][PADW];
    const int i0 = blockIdx.x * TMW, j0 = blockIdx.y * TMW;
    const int tx = threadIdx.x & 15, ty = threadIdx.x >> 4;
    float acc[4][4];
#pragma unroll
    for (int a = 0; a < 4; a++)
#pragma unroll
        for (int cc = 0; cc < 4; cc++) acc[a][cc] = 0.0f;
    for (int k0 = 0; k0 < DD; k0 += KTW) {
#pragma unroll
        for (int t = threadIdx.x; t < KTW * TMW; t += 256) {
            int rr = t >> 4, cc = t & 15;
            Us[cc][rr] = U[(i0 + rr) * DD + k0 + cc];
            Xs[cc][rr] = x[(j0 + rr) * DD + k0 + cc];
        }
        __syncthreads();
#pragma unroll
        for (int k = 0; k < KTW; k++) {
            float4 av = *(const float4*)&Us[k][ty * 4];
            float4 bv = *(const float4*)&Xs[k][tx * 4];
            float am[4] = {av.x, av.y, av.z, av.w};
            float bn[4] = {bv.x, bv.y, bv.z, bv.w};
#pragma unroll
            for (int mi = 0; mi < 4; mi++)
#pragma unroll
                for (int ni = 0; ni < 4; ni++) acc[mi][ni] += am[mi] * bn[ni];
        }
        __syncthreads();
    }
#pragma unroll
    for (int mi = 0; mi < 4; mi++) {
        const int i = i0 + ty * 4 + mi;
        const float bi = b[i];
#pragma unroll
        for (int ni = 0; ni < 4; ni++)
            g_Vx[i * BB + j0 + tx * 4 + ni] = acc[mi][ni] + bi;
    }
}

__device__ __forceinline__ void grid_barrier(unsigned& gen) {
    __syncthreads();
    if (threadIdx.x == 0) {
        gen++;
        __threadfence();
        unsigned prev = atomicAdd(&g_arrive, 1u);
        if (prev == SB - 1) {
            atomicExch(&g_arrive, 0u);
            __threadfence();
            atomicExch(&g_release, gen);
        } else {
            while (*(volatile unsigned*)&g_release < gen) { }
            __threadfence();
        }
    }
    __syncthreads();
}

// ------ persistent fp16 solver, 32x32 warp tiles + k-split, deep pipeline ---
__global__ void __launch_bounds__(256, 1) solve_kernel(float* __restrict__ out) {
    extern __shared__ __align__(16) char dsm[];
    const uint32_t sbase = (smem_u32(dsm) + 127u) & ~127u;
    __shared__ float sredD[8], sredN[8];

    const int tid = threadIdx.x, l = tid & 31, warp = tid >> 5;
    const int i0 = (blockIdx.x >> 2) * 64, j0 = (blockIdx.x & 3) * 64;
    const int pm = (warp >> 1) & 1;
    const int pn = warp & 1;
    const int ks = warp >> 2;
    const int r7 = l & 7;
    const int rA8 = ((l >> 3) & 1) * 8, selA = (l >> 4) & 1;
    const int rB8 = ((l >> 4) & 1) * 8, selB = (l >> 3) & 1;
    const int rowA0 = pm * 32 + r7 + rA8;
    const int rowB0 = pn * 32 + r7 + rB8;

    // ---- resident W: rows i0..i0+63, k < 768 (12 sub-chunks) ----
#pragma unroll
    for (int rep = 0; rep < 24; rep++) {
        const int idx = tid + rep * 256;          // 0..6143
        const int ch = idx >> 9;                  // sub-chunk 0..11
        const int rem = idx & 511;
        const int r_ = rem >> 3, c_ = rem & 7;
        cp16(sbase + (uint32_t)ch * SUBB + (uint32_t)r_ * 128 +
                 ((uint32_t)(c_ ^ (r_ & 7)) << 4),
             g_Wh + (long)(i0 + r_) * NN + ch * 64 + c_ * 8);
    }
    CP_COMMIT(); CP_WAIT(0); __syncthreads();

    const uint32_t O_RING = sbase + RESB;
    const int gk = ks * 2;

    float zr[2][2][2][2], vx[2][2][2][2];
#pragma unroll
    for (int f = 0; f < 2; f++)
#pragma unroll
        for (int gi = 0; gi < 2; gi++)
#pragma unroll
            for (int h = 0; h < 2; h++) {
                const int i = i0 + pm * 32 + f * 16 + h * 8 + (l >> 2);
                const int j = j0 + pn * 32 + (gk + gi) * 8 + (l & 3) * 2;
                float2 v = *(const float2*)&g_Vx[i * BB + j];
                vx[f][gi][h][0] = v.x; vx[f][gi][h][1] = v.y;
                zr[f][gi][h][0] = 0.0f; zr[f][gi][h][1] = 0.0f;
            }

#define STAGE_LOAD(kcn, zp) do {                                              \
    const int kn_ = (kcn);                                                    \
    const uint32_t st_ = O_RING + (uint32_t)((kn_) & (NSTG - 1)) * STGB;      \
    const int k0_ = kn_ * KC;                                                 \
    _Pragma("unroll")                                                         \
    for (int rep_ = 0; rep_ < 4; rep_++) {                                    \
        const int idx_ = tid + rep_ * 256;                                    \
        const int sub_ = idx_ >> 9;                                           \
        const int rem_ = idx_ & 511;                                          \
        const int r_ = rem_ >> 3, c_ = rem_ & 7;                              \
        const uint32_t d_ = (uint32_t)sub_ * SUBB + (uint32_t)r_ * 128 +      \
                            ((uint32_t)(c_ ^ (r_ & 7)) << 4);                 \
        if (kn_ >= RES_KC)                                                    \
            cp16(st_ + d_, g_Wh + (long)(i0 + r_) * NN + k0_ + sub_ * 64 + c_ * 8); \
        cp16(st_ + 2u * SUBB + d_,                                            \
             (zp) + (long)(j0 + r_) * NN + k0_ + sub_ * 64 + c_ * 8);         \
    } } while (0)

    unsigned gen = 0;
    int cur = 0, it = 0;

    while (1) {
        it++;
        const __half* __restrict__ zp = g_zh[cur];
        float c[2][4][4];
#pragma unroll
        for (int f = 0; f < 2; f++)
#pragma unroll
            for (int g = 0; g < 4; g++)
#pragma unroll
                for (int q = 0; q < 4; q++) c[f][g][q] = 0.0f;

        if (it > 1) {
#pragma unroll
            for (int s = 0; s < NSTG - 1; s++) { STAGE_LOAD(s, zp); CP_COMMIT(); }

            for (int kc = 0; kc < NKC; kc++) {
                CP_WAIT(NSTG - 2);
                __syncthreads();
                if (kc + NSTG - 1 < NKC) STAGE_LOAD(kc + NSTG - 1, zp);
                CP_COMMIT();

                const uint32_t rst = O_RING + (uint32_t)(kc & (NSTG - 1)) * STGB;
                const uint32_t abase = (kc < RES_KC)
                    ? sbase + (uint32_t)(2 * kc + ks) * SUBB
                    : rst + (uint32_t)ks * SUBB;
                const uint32_t bbase = rst + 2u * SUBB + (uint32_t)ks * SUBB;
#pragma unroll
                for (int s4 = 0; s4 < 4; s4++) {
                    const int kg0 = s4 * 2;
                    const uint32_t swA = (uint32_t)((kg0 + selA) ^ r7) << 4;
                    const uint32_t swB = (uint32_t)((kg0 + selB) ^ r7) << 4;
                    uint32_t ah0[4], ah1[4], bh0[4], bh1[4];
                    ldsm4(ah0, abase + (uint32_t)rowA0 * 128 + swA);
                    ldsm4(ah1, abase + (uint32_t)(rowA0 + 16) * 128 + swA);
                    ldsm4(bh0, bbase + (uint32_t)rowB0 * 128 + swB);
                    ldsm4(bh1, bbase + (uint32_t)(rowB0 + 16) * 128 + swB);
                    mma_hf(c[0][0], ah0, bh0[0], bh0[1]);
                    mma_hf(c[0][1], ah0, bh0[2], bh0[3]);
                    mma_hf(c[0][2], ah0, bh1[0], bh1[1]);
                    mma_hf(c[0][3], ah0, bh1[2], bh1[3]);
                    mma_hf(c[1][0], ah1, bh0[0], bh0[1]);
                    mma_hf(c[1][1], ah1, bh0[2], bh0[3]);
                    mma_hf(c[1][2], ah1, bh1[0], bh1[1]);
                    mma_hf(c[1][3], ah1, bh1[2], bh1[3]);
                }
            }

            // ---- k-split partial exchange (ring reused as buffer) ----
            CP_WAIT(0);
            __syncthreads();
            const uint32_t myslot = O_RING +
                (uint32_t)((((warp & 3) * 2 + ks) * 32 + l)) * 64u;
            const uint32_t prslot = O_RING +
                (uint32_t)((((warp & 3) * 2 + (1 - ks)) * 32 + l)) * 64u;
            const int go = (1 - ks) * 2;
#pragma unroll
            for (int f = 0; f < 2; f++)
#pragma unroll
                for (int gi = 0; gi < 2; gi++)
                    sts_v4(myslot + (uint32_t)(f * 2 + gi) * 16u, c[f][go + gi]);
            __syncthreads();
#pragma unroll
            for (int f = 0; f < 2; f++)
#pragma unroll
                for (int gi = 0; gi < 2; gi++) {
                    float v[4];
                    lds_v4(v, prslot + (uint32_t)(f * 2 + gi) * 16u);
#pragma unroll
                    for (int q = 0; q < 4; q++) c[f][gk + gi][q] += v[q];
                }
        }

        // ---- epilogue ----
        __half* __restrict__ zn = g_zh[cur ^ 1];
        float d2 = 0.0f, n2 = 0.0f;
#pragma unroll
        for (int f = 0; f < 2; f++)
#pragma unroll
            for (int gi = 0; gi < 2; gi++)
#pragma unroll
                for (int h = 0; h < 2; h++) {
                    const int i = i0 + pm * 32 + f * 16 + h * 8 + (l >> 2);
                    const int j = j0 + pn * 32 + (gk + gi) * 8 + (l & 3) * 2;
#pragma unroll
                    for (int p = 0; p < 2; p++) {
                        const float zv = zr[f][gi][h][p];
                        float v = 0.9f * zv +
                                  0.1f * (c[f][gk + gi][h * 2 + p] + vx[f][gi][h][p]);
                        float r = v > 0.0f ? v : 0.0f;
                        zr[f][gi][h][p] = r;
                        zn[(j + p) * NN + i] = __float2half_rn(r);
                        const float dd = r - zv;
                        d2 += dd * dd;
                        n2 += zv * zv;
                    }
                }
#pragma unroll
        for (int off = 16; off; off >>= 1) {
            d2 += __shfl_xor_sync(0xffffffffu, d2, off);
            n2 += __shfl_xor_sync(0xffffffffu, n2, off);
        }
        if (l == 0) { sredD[warp] = d2; sredN[warp] = n2; }
        __syncthreads();
        const int nb = it % 3;
        if (tid == 0) {
            double Dd = 0.0, Nd = 0.0;
#pragma unroll
            for (int w = 0; w < 8; w++) { Dd += (double)sredD[w]; Nd += (double)sredN[w]; }
            atomicAdd(&g_nd[nb][0], Dd);
            atomicAdd(&g_nd[nb][1], Nd);
        }

        grid_barrier(gen);

        const double Dt = *(volatile double*)&g_nd[nb][0];
        const double Nt = *(volatile double*)&g_nd[nb][1];
        const double err = sqrt(Dt) / (sqrt(Nt) + 1e-12);
        if (blockIdx.x == 0 && tid == 0) {
            const int rb = (it + 2) % 3;
            *(volatile double*)&g_nd[rb][0] = 0.0;
            *(volatile double*)&g_nd[rb][1] = 0.0;
            __threadfence();
        }
        cur ^= 1;
        if (it >= MAXIT || err < 1e-4) break;
    }
#undef STAGE_LOAD

#pragma unroll
    for (int f = 0; f < 2; f++)
#pragma unroll
        for (int gi = 0; gi < 2; gi++)
#pragma unroll
            for (int h = 0; h < 2; h++) {
                const int i = i0 + pm * 32 + f * 16 + h * 8 + (l >> 2);
                const int j = j0 + pn * 32 + (gk + gi) * 8 + (l & 3) * 2;
                float2 v;
                v.x = zr[f][gi][h][0];
                v.y = zr[f][gi][h][1];
                *(float2*)&out[i * BB + j] = v;
            }
}

extern "C" void kernel_launch(void* const* d_in, const int* in_sizes, int n_in,
                              void* d_out, int out_size) {
    const float* A     = (const float*)d_in[0];
    const float* S     = (const float*)d_in[1];
    const float* m_raw = (const float*)d_in[2];
    const float* U     = (const float*)d_in[3];
    const float* b     = (const float*)d_in[4];
    const float* x     = (const float*)d_in[5];
    float* out = (float*)d_out;

    cudaFuncSetAttribute(solve_kernel, cudaFuncAttributeMaxDynamicSharedMemorySize, DYN_SMEM);
    cudaFuncSetAttribute(build_w_mma_kernel, cudaFuncAttributeMaxDynamicSharedMemorySize, WDYN);

    init_small<<<1, 32>>>();
    dim3 gt(NN / 32, NN / 32);
    split_at_kernel<<<gt, 256>>>(A);
    dim3 gw(NN / 128, NN / 128);
    build_w_mma_kernel<<<gw, 256, WDYN>>>(S, m_raw);
    dim3 gv(NN / TMW, BB / TMW);
    build_vx_kernel<<<gv, 256>>>(U, b, x);
    solve_kernel<<<SB, 256, DYN_SMEM>>>(out);
}

// round 14
// speedup vs baseline: 1.9666x; 1.3311x over previous
#include <cuda_runtime.h>
#include <cuda_fp16.h>
#include <math.h>
#include <stdint.h>

#define NN 2048
#define BB 256
#define DD 512
#define MAXIT 300

// ---- solve: 32 m x 4 n = 128 CTAs; W k<1024 resident; KC=64, NSTG=6 --------
#define SB 128
#define KC 64
#define NKC 32
#define NSTG 6
#define SUBB 8192                 // 64 rows x 128B
#define RES_SUB 16                // resident chunks (k<1024)
#define RESB (RES_SUB*SUBB)       // 128KB
#define STGB (2*SUBB)             // stage: A + B = 16KB
#define DYN_SMEM (RESB + NSTG*STGB + 128)

// ---- build_w tiling --------------------------------------------------------
#define WNSTG 3
#define WMAT (128*128)
#define WSTG (2*WMAT)
#define WDYN (WNSTG*WSTG + 128)
#define WKC 64
#define WNKC (NN/WKC)

__device__ __half  g_Wh[NN*NN];
__device__ __half  g_Ath[NN*NN];
__device__ float   g_Vx[NN*BB];
__device__ __half  g_zh[2][BB*NN];
__device__ float   g_ns[2][SB][2];   // per-CTA norm slots {d2,n2}, 2-phase
__device__ unsigned g_arrive, g_release;

__device__ __forceinline__ uint32_t smem_u32(const void* p) {
    uint32_t a;
    asm("{ .reg .u64 t; cvta.to.shared.u64 t, %1; cvt.u32.u64 %0, t; }" : "=r"(a) : "l"(p));
    return a;
}
__device__ __forceinline__ void cp16(uint32_t dst, const void* src) {
    asm volatile("cp.async.cg.shared.global [%0], [%1], 16;" :: "r"(dst), "l"(src) : "memory");
}
#define CP_COMMIT() asm volatile("cp.async.commit_group;" ::: "memory")
#define CP_WAIT(n)  asm volatile("cp.async.wait_group %0;" :: "n"(n) : "memory")
__device__ __forceinline__ void ldsm4(uint32_t* r, uint32_t a) {
    asm volatile("ldmatrix.sync.aligned.m8n8.x4.shared.b16 {%0,%1,%2,%3}, [%4];"
                 : "=r"(r[0]), "=r"(r[1]), "=r"(r[2]), "=r"(r[3]) : "r"(a));
}
__device__ __forceinline__ void mma_hf(float* c, const uint32_t* a, uint32_t b0, uint32_t b1) {
    asm volatile("mma.sync.aligned.m16n8k16.row.col.f32.f16.f16.f32 "
                 "{%0,%1,%2,%3}, {%4,%5,%6,%7}, {%8,%9}, {%0,%1,%2,%3};"
                 : "+f"(c[0]), "+f"(c[1]), "+f"(c[2]), "+f"(c[3])
                 : "r"(a[0]), "r"(a[1]), "r"(a[2]), "r"(a[3]), "r"(b0), "r"(b1));
}
__device__ __forceinline__ void sts_v4(uint32_t a, const float* v) {
    asm volatile("st.shared.v4.f32 [%0], {%1,%2,%3,%4};"
                 :: "r"(a), "f"(v[0]), "f"(v[1]), "f"(v[2]), "f"(v[3]) : "memory");
}
__device__ __forceinline__ void lds_v4(float* v, uint32_t a) {
    asm volatile("ld.shared.v4.f32 {%0,%1,%2,%3}, [%4];"
                 : "=f"(v[0]), "=f"(v[1]), "=f"(v[2]), "=f"(v[3]) : "r"(a));
}

__global__ void init_small() {
    if (threadIdx.x == 0) { g_arrive = 0u; g_release = 0u; }
}

// At[i][k] = A[k][i] in fp16, 64x64 tiles
__global__ void __launch_bounds__(256) split_at_kernel(const float* __restrict__ A) {
    __shared__ float t[64][65];
    const int i0 = blockIdx.x * 64, k0 = blockIdx.y * 64;
    const int lx = threadIdx.x & 63, ly = threadIdx.x >> 6;
#pragma unroll
    for (int r = 0; r < 64; r += 4)
        t[ly + r][lx] = A[(long)(k0 + ly + r) * NN + i0 + lx];
    __syncthreads();
#pragma unroll
    for (int r = 0; r < 64; r += 4)
        g_Ath[(long)(i0 + ly + r) * NN + k0 + lx] = __float2half_rn(t[lx][ly + r]);
}

// W = (1-m)I - At At^T + S - S^T  (fp16 mma), output fp16
__global__ void __launch_bounds__(256, 1) build_w_mma_kernel(const float* __restrict__ S,
                                                             const float* __restrict__ m_raw) {
    extern __shared__ __align__(16) char dsm[];
    const uint32_t sbase = (smem_u32(dsm) + 127u) & ~127u;
    const int tid = threadIdx.x, l = tid & 31, warp = tid >> 5;
    const int i0 = blockIdx.x * 128, j0 = blockIdx.y * 128;
    const int wm = (warp >> 2) * 64, wn = (warp & 3) * 32;
    const int r7 = l & 7;
    const int rowA = wm + r7 + ((l >> 3) & 1) * 8;
    const int kgA = (l >> 4) & 1;
    const int rowBb = wn + r7 + ((l >> 4) & 1) * 8;
    const int kgB = (l >> 3) & 1;

    float c[4][4][4];
#pragma unroll
    for (int f = 0; f < 4; f++)
#pragma unroll
        for (int g = 0; g < 4; g++)
#pragma unroll
            for (int q = 0; q < 4; q++) c[f][g][q] = 0.0f;

#define W_LOAD(stg, k0v) do {                                                 \
    const uint32_t sb_ = sbase + (stg) * WSTG;                                \
    _Pragma("unroll")                                                         \
    for (int rep = 0; rep < 4; rep++) {                                       \
        const int idx_ = tid + rep * 256;                                     \
        const int r_ = idx_ >> 3, c_ = idx_ & 7;                              \
        const uint32_t d_ = (uint32_t)r_ * 128 + ((uint32_t)(c_ ^ (r_ & 7)) << 4); \
        cp16(sb_ + 0*WMAT + d_, g_Ath + (long)(i0 + r_) * NN + (k0v) + c_ * 8); \
        cp16(sb_ + 1*WMAT + d_, g_Ath + (long)(j0 + r_) * NN + (k0v) + c_ * 8); \
    } } while (0)

#pragma unroll
    for (int s = 0; s < WNSTG - 1; s++) { W_LOAD(s, s * WKC); CP_COMMIT(); }

    for (int kc = 0; kc < WNKC; kc++) {
        CP_WAIT(WNSTG - 2);
        __syncthreads();
        if (kc + WNSTG - 1 < WNKC) W_LOAD((kc + WNSTG - 1) % WNSTG, (kc + WNSTG - 1) * WKC);
        CP_COMMIT();
        const uint32_t sb = sbase + (kc % WNSTG) * WSTG;
#pragma unroll
        for (int s4 = 0; s4 < 4; s4++) {
            const int kg0 = s4 * 2;
            const uint32_t swA = (uint32_t)((kg0 + kgA) ^ r7) << 4;
            const uint32_t swB = (uint32_t)((kg0 + kgB) ^ r7) << 4;
            uint32_t ah[4][4], bh[2][4];
#pragma unroll
            for (int f = 0; f < 4; f++)
                ldsm4(ah[f], sb + 0*WMAT + (uint32_t)(rowA + f * 16) * 128 + swA);
#pragma unroll
            for (int g2 = 0; g2 < 2; g2++)
                ldsm4(bh[g2], sb + 1*WMAT + (uint32_t)(rowBb + g2 * 16) * 128 + swB);
#pragma unroll
            for (int f = 0; f < 4; f++)
#pragma unroll
                for (int g2 = 0; g2 < 2; g2++) {
                    mma_hf(c[f][g2*2+0], ah[f], bh[g2][0], bh[g2][1]);
                    mma_hf(c[f][g2*2+1], ah[f], bh[g2][2], bh[g2][3]);
                }
        }
    }
#undef W_LOAD

    const float m = log1pf(expf(m_raw[0]));
    const float omm = 1.0f - m;
#pragma unroll
    for (int f = 0; f < 4; f++)
#pragma unroll
        for (int g = 0; g < 4; g++)
#pragma unroll
            for (int h = 0; h < 2; h++) {
                const int i = i0 + wm + f * 16 + h * 8 + (l >> 2);
                const int j = j0 + wn + g * 8 + (l & 3) * 2;
                float2 sij = *(const float2*)&S[(long)i * NN + j];
                float w0 = -c[f][g][h*2+0] + sij.x - S[(long)j * NN + i];
                float w1 = -c[f][g][h*2+1] + sij.y - S[(long)(j + 1) * NN + i];
                if (i == j) w0 += omm;
                if (i == j + 1) w1 += omm;
                *(__half2*)&g_Wh[(long)i * NN + j] = __floats2half2_rn(w0, w1);
            }
}

#define TMW 64
#define KTW 16
#define PADW 68
__global__ void __launch_bounds__(256) build_vx_kernel(const float* __restrict__ U,
                                                       const float* __restrict__ b,
                                                       const float* __restrict__ x) {
    __shared__ __align__(16) float Us[KTW][PADW];
    __shared__ __align__(16) float Xs[KTW][PADW];
    const int i0 = blockIdx.x * TMW, j0 = blockIdx.y * TMW;
    const int tx = threadIdx.x & 15, ty = threadIdx.x >> 4;
    float acc[4][4];
#pragma unroll
    for (int a = 0; a < 4; a++)
#pragma unroll
        for (int cc = 0; cc < 4; cc++) acc[a][cc] = 0.0f;
    for (int k0 = 0; k0 < DD; k0 += KTW) {
#pragma unroll
        for (int t = threadIdx.x; t < KTW * TMW; t += 256) {
            int rr = t >> 4, cc = t & 15;
            Us[cc][rr] = U[(i0 + rr) * DD + k0 + cc];
            Xs[cc][rr] = x[(j0 + rr) * DD + k0 + cc];
        }
        __syncthreads();
#pragma unroll
        for (int k = 0; k < KTW; k++) {
            float4 av = *(const float4*)&Us[k][ty * 4];
            float4 bv = *(const float4*)&Xs[k][tx * 4];
            float am[4] = {av.x, av.y, av.z, av.w};
            float bn[4] = {bv.x, bv.y, bv.z, bv.w};
#pragma unroll
            for (int mi = 0; mi < 4; mi++)
#pragma unroll
                for (int ni = 0; ni < 4; ni++) acc[mi][ni] += am[mi] * bn[ni];
        }
        __syncthreads();
    }
#pragma unroll
    for (int mi = 0; mi < 4; mi++) {
        const int i = i0 + ty * 4 + mi;
        const float bi = b[i];
#pragma unroll
        for (int ni = 0; ni < 4; ni++)
            g_Vx[i * BB + j0 + tx * 4 + ni] = acc[mi][ni] + bi;
    }
}

__device__ __forceinline__ void grid_barrier(unsigned& gen) {
    __syncthreads();
    if (threadIdx.x == 0) {
        gen++;
        __threadfence();
        unsigned prev = atomicAdd(&g_arrive, 1u);
        if (prev == SB - 1) {
            atomicExch(&g_arrive, 0u);
            __threadfence();
            atomicExch(&g_release, gen);
        } else {
            while (*(volatile unsigned*)&g_release < gen) { }
            __threadfence();
        }
    }
    __syncthreads();
}

// ------ persistent fp16 solver: resident W(k<1024), KC=64 ring, slot norms --
__global__ void __launch_bounds__(256, 1) solve_kernel(float* __restrict__ out) {
    extern __shared__ __align__(16) char dsm[];
    const uint32_t sbase = (smem_u32(dsm) + 127u) & ~127u;
    __shared__ float sredD[8], sredN[8];
    __shared__ int s_stop;

    const int tid = threadIdx.x, l = tid & 31, warp = tid >> 5;
    const int i0 = (blockIdx.x >> 2) * 64, j0 = (blockIdx.x & 3) * 64;
    const int pm = (warp >> 1) & 1;
    const int pn = warp & 1;
    const int ks = warp >> 2;
    const int r7 = l & 7;
    const int rA8 = ((l >> 3) & 1) * 8, selA = (l >> 4) & 1;
    const int rB8 = ((l >> 4) & 1) * 8, selB = (l >> 3) & 1;
    const int rowA0 = pm * 32 + r7 + rA8;
    const int rowB0 = pn * 32 + r7 + rB8;

    // ---- resident W: rows i0..i0+63, k < 1024 (16 chunks of 8KB) ----
#pragma unroll
    for (int rep = 0; rep < 32; rep++) {
        const int idx = tid + rep * 256;
        const int ch = idx >> 9;
        const int rem = idx & 511;
        const int r_ = rem >> 3, c_ = rem & 7;
        cp16(sbase + (uint32_t)ch * SUBB + (uint32_t)r_ * 128 +
                 ((uint32_t)(c_ ^ (r_ & 7)) << 4),
             g_Wh + (long)(i0 + r_) * NN + ch * KC + c_ * 8);
    }
    CP_COMMIT(); CP_WAIT(0); __syncthreads();

    const uint32_t O_RING = sbase + RESB;
    const int gk = ks * 2;

    float zr[2][2][2][2], vx[2][2][2][2];
#pragma unroll
    for (int f = 0; f < 2; f++)
#pragma unroll
        for (int gi = 0; gi < 2; gi++)
#pragma unroll
            for (int h = 0; h < 2; h++) {
                const int i = i0 + pm * 32 + f * 16 + h * 8 + (l >> 2);
                const int j = j0 + pn * 32 + (gk + gi) * 8 + (l & 3) * 2;
                float2 v = *(const float2*)&g_Vx[i * BB + j];
                vx[f][gi][h][0] = v.x; vx[f][gi][h][1] = v.y;
                zr[f][gi][h][0] = 0.0f; zr[f][gi][h][1] = 0.0f;
            }

    // loader: 512 cp16 per matrix per stage -> 2 per thread
    const int ld_r0 = tid >> 3, ld_c = tid & 7;
    const uint32_t ld_d0 = (uint32_t)ld_r0 * 128 + ((uint32_t)(ld_c ^ (ld_r0 & 7)) << 4);
    const int ld_r1 = ld_r0 + 32;
    const uint32_t ld_d1 = (uint32_t)ld_r1 * 128 + ((uint32_t)(ld_c ^ (ld_r1 & 7)) << 4);

#define STAGE_LOAD(kcn, zp) do {                                              \
    const int kn_ = (kcn);                                                    \
    const uint32_t st_ = O_RING + (uint32_t)((kn_) % NSTG) * STGB;            \
    const int k0_ = kn_ * KC;                                                 \
    if (kn_ >= RES_SUB) {                                                     \
        cp16(st_ + ld_d0, g_Wh + (long)(i0 + ld_r0) * NN + k0_ + ld_c * 8);   \
        cp16(st_ + ld_d1, g_Wh + (long)(i0 + ld_r1) * NN + k0_ + ld_c * 8);   \
    }                                                                         \
    cp16(st_ + SUBB + ld_d0, (zp) + (long)(j0 + ld_r0) * NN + k0_ + ld_c * 8);\
    cp16(st_ + SUBB + ld_d1, (zp) + (long)(j0 + ld_r1) * NN + k0_ + ld_c * 8);\
    } while (0)

    unsigned gen = 0;
    int cur = 0, it = 0;

    while (1) {
        it++;
        const __half* __restrict__ zp = g_zh[cur];
        float c[2][4][4];
#pragma unroll
        for (int f = 0; f < 2; f++)
#pragma unroll
            for (int g = 0; g < 4; g++)
#pragma unroll
                for (int q = 0; q < 4; q++) c[f][g][q] = 0.0f;

        if (it > 1) {
#pragma unroll
            for (int s = 0; s < NSTG - 1; s++) { STAGE_LOAD(s, zp); CP_COMMIT(); }

            for (int kc = 0; kc < NKC; kc++) {
                CP_WAIT(NSTG - 2);
                __syncthreads();
                if (kc + NSTG - 1 < NKC) STAGE_LOAD(kc + NSTG - 1, zp);
                CP_COMMIT();

                const uint32_t rst = O_RING + (uint32_t)(kc % NSTG) * STGB;
                const uint32_t abase = (kc < RES_SUB)
                    ? sbase + (uint32_t)kc * SUBB
                    : rst;
                const uint32_t bbase = rst + SUBB;
#pragma unroll
                for (int s4 = 0; s4 < 2; s4++) {
                    const int kg0 = (ks * 2 + s4) * 2;
                    const uint32_t swA = (uint32_t)((kg0 + selA) ^ r7) << 4;
                    const uint32_t swB = (uint32_t)((kg0 + selB) ^ r7) << 4;
                    uint32_t ah0[4], ah1[4], bh0[4], bh1[4];
                    ldsm4(ah0, abase + (uint32_t)rowA0 * 128 + swA);
                    ldsm4(ah1, abase + (uint32_t)(rowA0 + 16) * 128 + swA);
                    ldsm4(bh0, bbase + (uint32_t)rowB0 * 128 + swB);
                    ldsm4(bh1, bbase + (uint32_t)(rowB0 + 16) * 128 + swB);
                    mma_hf(c[0][0], ah0, bh0[0], bh0[1]);
                    mma_hf(c[0][1], ah0, bh0[2], bh0[3]);
                    mma_hf(c[0][2], ah0, bh1[0], bh1[1]);
                    mma_hf(c[0][3], ah0, bh1[2], bh1[3]);
                    mma_hf(c[1][0], ah1, bh0[0], bh0[1]);
                    mma_hf(c[1][1], ah1, bh0[2], bh0[3]);
                    mma_hf(c[1][2], ah1, bh1[0], bh1[1]);
                    mma_hf(c[1][3], ah1, bh1[2], bh1[3]);
                }
            }

            // ---- k-split partial exchange (ring reused as buffer) ----
            CP_WAIT(0);
            __syncthreads();
            const uint32_t myslot = O_RING +
                (uint32_t)((((warp & 3) * 2 + ks) * 32 + l)) * 64u;
            const uint32_t prslot = O_RING +
                (uint32_t)((((warp & 3) * 2 + (1 - ks)) * 32 + l)) * 64u;
            const int go = (1 - ks) * 2;
#pragma unroll
            for (int f = 0; f < 2; f++)
#pragma unroll
                for (int gi = 0; gi < 2; gi++)
                    sts_v4(myslot + (uint32_t)(f * 2 + gi) * 16u, c[f][go + gi]);
            __syncthreads();
#pragma unroll
            for (int f = 0; f < 2; f++)
#pragma unroll
                for (int gi = 0; gi < 2; gi++) {
                    float v[4];
                    lds_v4(v, prslot + (uint32_t)(f * 2 + gi) * 16u);
#pragma unroll
                    for (int q = 0; q < 4; q++) c[f][gk + gi][q] += v[q];
                }
        }

        // ---- epilogue ----
        __half* __restrict__ zn = g_zh[cur ^ 1];
        float d2 = 0.0f, n2 = 0.0f;
#pragma unroll
        for (int f = 0; f < 2; f++)
#pragma unroll
            for (int gi = 0; gi < 2; gi++)
#pragma unroll
                for (int h = 0; h < 2; h++) {
                    const int i = i0 + pm * 32 + f * 16 + h * 8 + (l >> 2);
                    const int j = j0 + pn * 32 + (gk + gi) * 8 + (l & 3) * 2;
#pragma unroll
                    for (int p = 0; p < 2; p++) {
                        const float zv = zr[f][gi][h][p];
                        float v = 0.9f * zv +
                                  0.1f * (c[f][gk + gi][h * 2 + p] + vx[f][gi][h][p]);
                        float r = v > 0.0f ? v : 0.0f;
                        zr[f][gi][h][p] = r;
                        zn[(j + p) * NN + i] = __float2half_rn(r);
                        const float dd = r - zv;
                        d2 += dd * dd;
                        n2 += zv * zv;
                    }
                }
#pragma unroll
        for (int off = 16; off; off >>= 1) {
            d2 += __shfl_xor_sync(0xffffffffu, d2, off);
            n2 += __shfl_xor_sync(0xffffffffu, n2, off);
        }
        if (l == 0) { sredD[warp] = d2; sredN[warp] = n2; }
        __syncthreads();
        const int ph = it & 1;
        if (tid == 0) {
            float Dd = 0.0f, Nd = 0.0f;
#pragma unroll
            for (int w = 0; w < 8; w++) { Dd += sredD[w]; Nd += sredN[w]; }
            g_ns[ph][blockIdx.x][0] = Dd;
            g_ns[ph][blockIdx.x][1] = Nd;
        }

        grid_barrier(gen);   // publishes all slots (fence inside barrier)

        // ---- slot reduction: every CTA computes the stop decision ----
        {
            float d2s = 0.0f, n2s = 0.0f;
            if (tid < SB) {
                float2 sv = *(const float2*)&g_ns[ph][tid][0];
                d2s = sv.x; n2s = sv.y;
            }
#pragma unroll
            for (int off = 16; off; off >>= 1) {
                d2s += __shfl_xor_sync(0xffffffffu, d2s, off);
                n2s += __shfl_xor_sync(0xffffffffu, n2s, off);
            }
            if (l == 0) { sredD[warp] = d2s; sredN[warp] = n2s; }
            __syncthreads();
            if (tid == 0) {
                float Dt = 0.0f, Nt = 0.0f;
#pragma unroll
                for (int w = 0; w < 4; w++) { Dt += sredD[w]; Nt += sredN[w]; }
                const float err = sqrtf(Dt) / (sqrtf(Nt) + 1e-12f);
                s_stop = (it >= MAXIT || err < 1e-4f) ? 1 : 0;
            }
            __syncthreads();
        }
        cur ^= 1;
        if (s_stop) break;
    }
#undef STAGE_LOAD

#pragma unroll
    for (int f = 0; f < 2; f++)
#pragma unroll
        for (int gi = 0; gi < 2; gi++)
#pragma unroll
            for (int h = 0; h < 2; h++) {
                const int i = i0 + pm * 32 + f * 16 + h * 8 + (l >> 2);
                const int j = j0 + pn * 32 + (gk + gi) * 8 + (l & 3) * 2;
                float2 v;
                v.x = zr[f][gi][h][0];
                v.y = zr[f][gi][h][1];
                *(float2*)&out[i * BB + j] = v;
            }
}

extern "C" void kernel_launch(void* const* d_in, const int* in_sizes, int n_in,
                              void* d_out, int out_size) {
    const float* A     = (const float*)d_in[0];
    const float* S     = (const float*)d_in[1];
    const float* m_raw = (const float*)d_in[2];
    const float* U     = (const float*)d_in[3];
    const float* b     = (const float*)d_in[4];
    const float* x     = (const float*)d_in[5];
    float* out = (float*)d_out;

    cudaFuncSetAttribute(solve_kernel, cudaFuncAttributeMaxDynamicSharedMemorySize, DYN_SMEM);
    cudaFuncSetAttribute(build_w_mma_kernel, cudaFuncAttributeMaxDynamicSharedMemorySize, WDYN);

    init_small<<<1, 32>>>();
    dim3 gt(NN / 64, NN / 64);
    split_at_kernel<<<gt, 256>>>(A);
    dim3 gw(NN / 128, NN / 128);
    build_w_mma_kernel<<<gw, 256, WDYN>>>(S, m_raw);
    dim3 gv(NN / TMW, BB / TMW);
    build_vx_kernel<<<gv, 256>>>(U, b, x);
    solve_kernel<<<SB, 256, DYN_SMEM>>>(out);
}

// round 15
// speedup vs baseline: 2.0151x; 1.0246x over previous
#include <cuda_runtime.h>
#include <cuda_fp16.h>
#include <math.h>
#include <stdint.h>

#define NN 2048
#define BB 256
#define DD 512
#define MAXIT 300

// ---- solve: 32 m x 4 n = 128 CTAs; W k<1152 resident; KC=64, NSTG=5 --------
#define SB 128
#define KC 64
#define NKC 32
#define NSTG 5
#define SUBB 8192                 // 64 rows x 128B
#define RES_SUB 18                // resident chunks (k<1152)
#define RESB (RES_SUB*SUBB)       // 144KB
#define STGB (2*SUBB)             // stage: A + B = 16KB
#define DYN_SMEM (RESB + NSTG*STGB + 128)

// ---- build_w tiling --------------------------------------------------------
#define WNSTG 3
#define WMAT (128*128)
#define WSTG (2*WMAT)
#define WDYN (WNSTG*WSTG + 128)
#define WKC 64
#define WNKC (NN/WKC)

__device__ __half  g_Wh[NN*NN];
__device__ __half  g_Ath[NN*NN];
__device__ float   g_Vx[NN*BB];
__device__ __half  g_zh[2][BB*NN];
__device__ float   g_ns[2][SB][2];   // per-CTA norm slots {d2,n2}, 2-phase
__device__ unsigned g_arrive, g_release;

__device__ __forceinline__ uint32_t smem_u32(const void* p) {
    uint32_t a;
    asm("{ .reg .u64 t; cvta.to.shared.u64 t, %1; cvt.u32.u64 %0, t; }" : "=r"(a) : "l"(p));
    return a;
}
__device__ __forceinline__ void cp16(uint32_t dst, const void* src) {
    asm volatile("cp.async.cg.shared.global [%0], [%1], 16;" :: "r"(dst), "l"(src) : "memory");
}
#define CP_COMMIT() asm volatile("cp.async.commit_group;" ::: "memory")
#define CP_WAIT(n)  asm volatile("cp.async.wait_group %0;" :: "n"(n) : "memory")
__device__ __forceinline__ void ldsm4(uint32_t* r, uint32_t a) {
    asm volatile("ldmatrix.sync.aligned.m8n8.x4.shared.b16 {%0,%1,%2,%3}, [%4];"
                 : "=r"(r[0]), "=r"(r[1]), "=r"(r[2]), "=r"(r[3]) : "r"(a));
}
__device__ __forceinline__ void mma_hf(float* c, const uint32_t* a, uint32_t b0, uint32_t b1) {
    asm volatile("mma.sync.aligned.m16n8k16.row.col.f32.f16.f16.f32 "
                 "{%0,%1,%2,%3}, {%4,%5,%6,%7}, {%8,%9}, {%0,%1,%2,%3};"
                 : "+f"(c[0]), "+f"(c[1]), "+f"(c[2]), "+f"(c[3])
                 : "r"(a[0]), "r"(a[1]), "r"(a[2]), "r"(a[3]), "r"(b0), "r"(b1));
}
__device__ __forceinline__ void sts_v4(uint32_t a, const float* v) {
    asm volatile("st.shared.v4.f32 [%0], {%1,%2,%3,%4};"
                 :: "r"(a), "f"(v[0]), "f"(v[1]), "f"(v[2]), "f"(v[3]) : "memory");
}
__device__ __forceinline__ void lds_v4(float* v, uint32_t a) {
    asm volatile("ld.shared.v4.f32 {%0,%1,%2,%3}, [%4];"
                 : "=f"(v[0]), "=f"(v[1]), "=f"(v[2]), "=f"(v[3]) : "r"(a));
}

__global__ void init_small() {
    if (threadIdx.x == 0) { g_arrive = 0u; g_release = 0u; }
}

// At[i][k] = A[k][i] in fp16, 64x64 tiles
__global__ void __launch_bounds__(256) split_at_kernel(const float* __restrict__ A) {
    __shared__ float t[64][65];
    const int i0 = blockIdx.x * 64, k0 = blockIdx.y * 64;
    const int lx = threadIdx.x & 63, ly = threadIdx.x >> 6;
#pragma unroll
    for (int r = 0; r < 64; r += 4)
        t[ly + r][lx] = A[(long)(k0 + ly + r) * NN + i0 + lx];
    __syncthreads();
#pragma unroll
    for (int r = 0; r < 64; r += 4)
        g_Ath[(long)(i0 + ly + r) * NN + k0 + lx] = __float2half_rn(t[lx][ly + r]);
}

// W = (1-m)I - At At^T + S - S^T  (fp16 mma), symmetric: only bi<=bj blocks.
// For off-diagonal blocks also writes the transposed block:
//   w   = -c + S[i][j] - S[j][i]      (i block bi, j block bj)
//   wT  = -c + S[j][i] - S[i][j] = -2c - w
__global__ void __launch_bounds__(256, 1) build_w_mma_kernel(const float* __restrict__ S,
                                                             const float* __restrict__ m_raw) {
    extern __shared__ __align__(16) char dsm[];
    const uint32_t sbase = (smem_u32(dsm) + 127u) & ~127u;
    const int tid = threadIdx.x, l = tid & 31, warp = tid >> 5;

    // decode triangular block index (bi <= bj), 16x17/2 = 136 blocks
    int bi = 0, rem = blockIdx.x;
    while (rem >= 16 - bi) { rem -= 16 - bi; bi++; }
    const int bj = bi + rem;
    const int i0 = bi * 128, j0 = bj * 128;

    const int wm = (warp >> 2) * 64, wn = (warp & 3) * 32;
    const int r7 = l & 7;
    const int rowA = wm + r7 + ((l >> 3) & 1) * 8;
    const int kgA = (l >> 4) & 1;
    const int rowBb = wn + r7 + ((l >> 4) & 1) * 8;
    const int kgB = (l >> 3) & 1;

    float c[4][4][4];
#pragma unroll
    for (int f = 0; f < 4; f++)
#pragma unroll
        for (int g = 0; g < 4; g++)
#pragma unroll
            for (int q = 0; q < 4; q++) c[f][g][q] = 0.0f;

#define W_LOAD(stg, k0v) do {                                                 \
    const uint32_t sb_ = sbase + (stg) * WSTG;                                \
    _Pragma("unroll")                                                         \
    for (int rep = 0; rep < 4; rep++) {                                       \
        const int idx_ = tid + rep * 256;                                     \
        const int r_ = idx_ >> 3, c_ = idx_ & 7;                              \
        const uint32_t d_ = (uint32_t)r_ * 128 + ((uint32_t)(c_ ^ (r_ & 7)) << 4); \
        cp16(sb_ + 0*WMAT + d_, g_Ath + (long)(i0 + r_) * NN + (k0v) + c_ * 8); \
        cp16(sb_ + 1*WMAT + d_, g_Ath + (long)(j0 + r_) * NN + (k0v) + c_ * 8); \
    } } while (0)

#pragma unroll
    for (int s = 0; s < WNSTG - 1; s++) { W_LOAD(s, s * WKC); CP_COMMIT(); }

    for (int kc = 0; kc < WNKC; kc++) {
        CP_WAIT(WNSTG - 2);
        __syncthreads();
        if (kc + WNSTG - 1 < WNKC) W_LOAD((kc + WNSTG - 1) % WNSTG, (kc + WNSTG - 1) * WKC);
        CP_COMMIT();
        const uint32_t sb = sbase + (kc % WNSTG) * WSTG;
#pragma unroll
        for (int s4 = 0; s4 < 4; s4++) {
            const int kg0 = s4 * 2;
            const uint32_t swA = (uint32_t)((kg0 + kgA) ^ r7) << 4;
            const uint32_t swB = (uint32_t)((kg0 + kgB) ^ r7) << 4;
            uint32_t ah[4][4], bh[2][4];
#pragma unroll
            for (int f = 0; f < 4; f++)
                ldsm4(ah[f], sb + 0*WMAT + (uint32_t)(rowA + f * 16) * 128 + swA);
#pragma unroll
            for (int g2 = 0; g2 < 2; g2++)
                ldsm4(bh[g2], sb + 1*WMAT + (uint32_t)(rowBb + g2 * 16) * 128 + swB);
#pragma unroll
            for (int f = 0; f < 4; f++)
#pragma unroll
                for (int g2 = 0; g2 < 2; g2++) {
                    mma_hf(c[f][g2*2+0], ah[f], bh[g2][0], bh[g2][1]);
                    mma_hf(c[f][g2*2+1], ah[f], bh[g2][2], bh[g2][3]);
                }
        }
    }
#undef W_LOAD

    const float m = log1pf(expf(m_raw[0]));
    const float omm = 1.0f - m;
#pragma unroll
    for (int f = 0; f < 4; f++)
#pragma unroll
        for (int g = 0; g < 4; g++)
#pragma unroll
            for (int h = 0; h < 2; h++) {
                const int i = i0 + wm + f * 16 + h * 8 + (l >> 2);
                const int j = j0 + wn + g * 8 + (l & 3) * 2;
                const float c0 = c[f][g][h*2+0], c1 = c[f][g][h*2+1];
                float2 sij = *(const float2*)&S[(long)i * NN + j];
                float w0 = -c0 + sij.x - S[(long)j * NN + i];
                float w1 = -c1 + sij.y - S[(long)(j + 1) * NN + i];
                if (i == j) w0 += omm;
                if (i == j + 1) w1 += omm;
                *(__half2*)&g_Wh[(long)i * NN + j] = __floats2half2_rn(w0, w1);
                if (bi != bj) {
                    // transposed block: wT = -2c - w
                    g_Wh[(long)j * NN + i]       = __float2half_rn(-2.0f * c0 - w0);
                    g_Wh[(long)(j + 1) * NN + i] = __float2half_rn(-2.0f * c1 - w1);
                }
            }
}

#define TMW 64
#define KTW 16
#define PADW 68
__global__ void __launch_bounds__(256) build_vx_kernel(const float* __restrict__ U,
                                                       const float* __restrict__ b,
                                                       const float* __restrict__ x) {
    __shared__ __align__(16) float Us[KTW][PADW];
    __shared__ __align__(16) float Xs[KTW][PADW];
    const int i0 = blockIdx.x * TMW, j0 = blockIdx.y * TMW;
    const int tx = threadIdx.x & 15, ty = threadIdx.x >> 4;
    float acc[4][4];
#pragma unroll
    for (int a = 0; a < 4; a++)
#pragma unroll
        for (int cc = 0; cc < 4; cc++) acc[a][cc] = 0.0f;
    for (int k0 = 0; k0 < DD; k0 += KTW) {
#pragma unroll
        for (int t = threadIdx.x; t < KTW * TMW; t += 256) {
            int rr = t >> 4, cc = t & 15;
            Us[cc][rr] = U[(i0 + rr) * DD + k0 + cc];
            Xs[cc][rr] = x[(j0 + rr) * DD + k0 + cc];
        }
        __syncthreads();
#pragma unroll
        for (int k = 0; k < KTW; k++) {
            float4 av = *(const float4*)&Us[k][ty * 4];
            float4 bv = *(const float4*)&Xs[k][tx * 4];
            float am[4] = {av.x, av.y, av.z, av.w};
            float bn[4] = {bv.x, bv.y, bv.z, bv.w};
#pragma unroll
            for (int mi = 0; mi < 4; mi++)
#pragma unroll
                for (int ni = 0; ni < 4; ni++) acc[mi][ni] += am[mi] * bn[ni];
        }
        __syncthreads();
    }
#pragma unroll
    for (int mi = 0; mi < 4; mi++) {
        const int i = i0 + ty * 4 + mi;
        const float bi = b[i];
#pragma unroll
        for (int ni = 0; ni < 4; ni++)
            g_Vx[i * BB + j0 + tx * 4 + ni] = acc[mi][ni] + bi;
    }
}

__device__ __forceinline__ void grid_barrier(unsigned& gen) {
    __syncthreads();
    if (threadIdx.x == 0) {
        gen++;
        __threadfence();
        unsigned prev = atomicAdd(&g_arrive, 1u);
        if (prev == SB - 1) {
            atomicExch(&g_arrive, 0u);
            __threadfence();
            atomicExch(&g_release, gen);
        } else {
            while (*(volatile unsigned*)&g_release < gen) { }
            __threadfence();
        }
    }
    __syncthreads();
}

// ------ persistent fp16 solver: resident W(k<1152), KC=64 ring, slot norms --
__global__ void __launch_bounds__(256, 1) solve_kernel(float* __restrict__ out) {
    extern __shared__ __align__(16) char dsm[];
    const uint32_t sbase = (smem_u32(dsm) + 127u) & ~127u;
    __shared__ float sredD[8], sredN[8];
    __shared__ int s_stop;

    const int tid = threadIdx.x, l = tid & 31, warp = tid >> 5;
    const int i0 = (blockIdx.x >> 2) * 64, j0 = (blockIdx.x & 3) * 64;
    const int pm = (warp >> 1) & 1;
    const int pn = warp & 1;
    const int ks = warp >> 2;
    const int r7 = l & 7;
    const int rA8 = ((l >> 3) & 1) * 8, selA = (l >> 4) & 1;
    const int rB8 = ((l >> 4) & 1) * 8, selB = (l >> 3) & 1;
    const int rowA0 = pm * 32 + r7 + rA8;
    const int rowB0 = pn * 32 + r7 + rB8;

    // ---- resident W: rows i0..i0+63, k < 1152 (18 chunks of 8KB) ----
#pragma unroll
    for (int rep = 0; rep < 36; rep++) {
        const int idx = tid + rep * 256;          // 0..9215
        const int ch = idx >> 9;                  // chunk 0..17
        const int rem = idx & 511;
        const int r_ = rem >> 3, c_ = rem & 7;
        cp16(sbase + (uint32_t)ch * SUBB + (uint32_t)r_ * 128 +
                 ((uint32_t)(c_ ^ (r_ & 7)) << 4),
             g_Wh + (long)(i0 + r_) * NN + ch * KC + c_ * 8);
    }
    CP_COMMIT(); CP_WAIT(0); __syncthreads();

    const uint32_t O_RING = sbase + RESB;
    const int gk = ks * 2;

    float zr[2][2][2][2], vx[2][2][2][2];
#pragma unroll
    for (int f = 0; f < 2; f++)
#pragma unroll
        for (int gi = 0; gi < 2; gi++)
#pragma unroll
            for (int h = 0; h < 2; h++) {
                const int i = i0 + pm * 32 + f * 16 + h * 8 + (l >> 2);
                const int j = j0 + pn * 32 + (gk + gi) * 8 + (l & 3) * 2;
                float2 v = *(const float2*)&g_Vx[i * BB + j];
                vx[f][gi][h][0] = v.x; vx[f][gi][h][1] = v.y;
                zr[f][gi][h][0] = 0.0f; zr[f][gi][h][1] = 0.0f;
            }

    const int ld_r0 = tid >> 3, ld_c = tid & 7;
    const uint32_t ld_d0 = (uint32_t)ld_r0 * 128 + ((uint32_t)(ld_c ^ (ld_r0 & 7)) << 4);
    const int ld_r1 = ld_r0 + 32;
    const uint32_t ld_d1 = (uint32_t)ld_r1 * 128 + ((uint32_t)(ld_c ^ (ld_r1 & 7)) << 4);

#define STAGE_LOAD(kcn, zp) do {                                              \
    const int kn_ = (kcn);                                                    \
    const uint32_t st_ = O_RING + (uint32_t)((kn_) % NSTG) * STGB;            \
    const int k0_ = kn_ * KC;                                                 \
    if (kn_ >= RES_SUB) {                                                     \
        cp16(st_ + ld_d0, g_Wh + (long)(i0 + ld_r0) * NN + k0_ + ld_c * 8);   \
        cp16(st_ + ld_d1, g_Wh + (long)(i0 + ld_r1) * NN + k0_ + ld_c * 8);   \
    }                                                                         \
    cp16(st_ + SUBB + ld_d0, (zp) + (long)(j0 + ld_r0) * NN + k0_ + ld_c * 8);\
    cp16(st_ + SUBB + ld_d1, (zp) + (long)(j0 + ld_r1) * NN + k0_ + ld_c * 8);\
    } while (0)

    unsigned gen = 0;
    int cur = 0, it = 0;

    while (1) {
        it++;
        const __half* __restrict__ zp = g_zh[cur];
        float c[2][4][4];
#pragma unroll
        for (int f = 0; f < 2; f++)
#pragma unroll
            for (int g = 0; g < 4; g++)
#pragma unroll
                for (int q = 0; q < 4; q++) c[f][g][q] = 0.0f;

        if (it > 1) {
#pragma unroll
            for (int s = 0; s < NSTG - 1; s++) { STAGE_LOAD(s, zp); CP_COMMIT(); }

            for (int kc = 0; kc < NKC; kc++) {
                CP_WAIT(NSTG - 2);
                __syncthreads();
                if (kc + NSTG - 1 < NKC) STAGE_LOAD(kc + NSTG - 1, zp);
                CP_COMMIT();

                const uint32_t rst = O_RING + (uint32_t)(kc % NSTG) * STGB;
                const uint32_t abase = (kc < RES_SUB)
                    ? sbase + (uint32_t)kc * SUBB
                    : rst;
                const uint32_t bbase = rst + SUBB;
#pragma unroll
                for (int s4 = 0; s4 < 2; s4++) {
                    const int kg0 = (ks * 2 + s4) * 2;
                    const uint32_t swA = (uint32_t)((kg0 + selA) ^ r7) << 4;
                    const uint32_t swB = (uint32_t)((kg0 + selB) ^ r7) << 4;
                    uint32_t ah0[4], ah1[4], bh0[4], bh1[4];
                    ldsm4(ah0, abase + (uint32_t)rowA0 * 128 + swA);
                    ldsm4(ah1, abase + (uint32_t)(rowA0 + 16) * 128 + swA);
                    ldsm4(bh0, bbase + (uint32_t)rowB0 * 128 + swB);
                    ldsm4(bh1, bbase + (uint32_t)(rowB0 + 16) * 128 + swB);
                    mma_hf(c[0][0], ah0, bh0[0], bh0[1]);
                    mma_hf(c[0][1], ah0, bh0[2], bh0[3]);
                    mma_hf(c[0][2], ah0, bh1[0], bh1[1]);
                    mma_hf(c[0][3], ah0, bh1[2], bh1[3]);
                    mma_hf(c[1][0], ah1, bh0[0], bh0[1]);
                    mma_hf(c[1][1], ah1, bh0[2], bh0[3]);
                    mma_hf(c[1][2], ah1, bh1[0], bh1[1]);
                    mma_hf(c[1][3], ah1, bh1[2], bh1[3]);
                }
            }

            // ---- k-split partial exchange (ring reused as buffer) ----
            CP_WAIT(0);
            __syncthreads();
            const uint32_t myslot = O_RING +
                (uint32_t)((((warp & 3) * 2 + ks) * 32 + l)) * 64u;
            const uint32_t prslot = O_RING +
                (uint32_t)((((warp & 3) * 2 + (1 - ks)) * 32 + l)) * 64u;
            const int go = (1 - ks) * 2;
#pragma unroll
            for (int f = 0; f < 2; f++)
#pragma unroll
                for (int gi = 0; gi < 2; gi++)
                    sts_v4(myslot + (uint32_t)(f * 2 + gi) * 16u, c[f][go + gi]);
            __syncthreads();
#pragma unroll
            for (int f = 0; f < 2; f++)
#pragma unroll
                for (int gi = 0; gi < 2; gi++) {
                    float v[4];
                    lds_v4(v, prslot + (uint32_t)(f * 2 + gi) * 16u);
#pragma unroll
                    for (int q = 0; q < 4; q++) c[f][gk + gi][q] += v[q];
                }
        }

        // ---- epilogue ----
        __half* __restrict__ zn = g_zh[cur ^ 1];
        float d2 = 0.0f, n2 = 0.0f;
#pragma unroll
        for (int f = 0; f < 2; f++)
#pragma unroll
            for (int gi = 0; gi < 2; gi++)
#pragma unroll
                for (int h = 0; h < 2; h++) {
                    const int i = i0 + pm * 32 + f * 16 + h * 8 + (l >> 2);
                    const int j = j0 + pn * 32 + (gk + gi) * 8 + (l & 3) * 2;
#pragma unroll
                    for (int p = 0; p < 2; p++) {
                        const float zv = zr[f][gi][h][p];
                        float v = 0.9f * zv +
                                  0.1f * (c[f][gk + gi][h * 2 + p] + vx[f][gi][h][p]);
                        float r = v > 0.0f ? v : 0.0f;
                        zr[f][gi][h][p] = r;
                        zn[(j + p) * NN + i] = __float2half_rn(r);
                        const float dd = r - zv;
                        d2 += dd * dd;
                        n2 += zv * zv;
                    }
                }
#pragma unroll
        for (int off = 16; off; off >>= 1) {
            d2 += __shfl_xor_sync(0xffffffffu, d2, off);
            n2 += __shfl_xor_sync(0xffffffffu, n2, off);
        }
        if (l == 0) { sredD[warp] = d2; sredN[warp] = n2; }
        __syncthreads();
        const int ph = it & 1;
        if (tid == 0) {
            float Dd = 0.0f, Nd = 0.0f;
#pragma unroll
            for (int w = 0; w < 8; w++) { Dd += sredD[w]; Nd += sredN[w]; }
            g_ns[ph][blockIdx.x][0] = Dd;
            g_ns[ph][blockIdx.x][1] = Nd;
        }

        grid_barrier(gen);

        // ---- slot reduction: every CTA computes the stop decision ----
        {
            float d2s = 0.0f, n2s = 0.0f;
            if (tid < SB) {
                float2 sv = *(const float2*)&g_ns[ph][tid][0];
                d2s = sv.x; n2s = sv.y;
            }
#pragma unroll
            for (int off = 16; off; off >>= 1) {
                d2s += __shfl_xor_sync(0xffffffffu, d2s, off);
                n2s += __shfl_xor_sync(0xffffffffu, n2s, off);
            }
            if (l == 0) { sredD[warp] = d2s; sredN[warp] = n2s; }
            __syncthreads();
            if (tid == 0) {
                float Dt = 0.0f, Nt = 0.0f;
#pragma unroll
                for (int w = 0; w < 4; w++) { Dt += sredD[w]; Nt += sredN[w]; }
                const float err = sqrtf(Dt) / (sqrtf(Nt) + 1e-12f);
                s_stop = (it >= MAXIT || err < 1e-4f) ? 1 : 0;
            }
            __syncthreads();
        }
        cur ^= 1;
        if (s_stop) break;
    }
#undef STAGE_LOAD

#pragma unroll
    for (int f = 0; f < 2; f++)
#pragma unroll
        for (int gi = 0; gi < 2; gi++)
#pragma unroll
            for (int h = 0; h < 2; h++) {
                const int i = i0 + pm * 32 + f * 16 + h * 8 + (l >> 2);
                const int j = j0 + pn * 32 + (gk + gi) * 8 + (l & 3) * 2;
                float2 v;
                v.x = zr[f][gi][h][0];
                v.y = zr[f][gi][h][1];
                *(float2*)&out[i * BB + j] = v;
            }
}

extern "C" void kernel_launch(void* const* d_in, const int* in_sizes, int n_in,
                              void* d_out, int out_size) {
    const float* A     = (const float*)d_in[0];
    const float* S     = (const float*)d_in[1];
    const float* m_raw = (const float*)d_in[2];
    const float* U     = (const float*)d_in[3];
    const float* b     = (const float*)d_in[4];
    const float* x     = (const float*)d_in[5];
    float* out = (float*)d_out;

    cudaFuncSetAttribute(solve_kernel, cudaFuncAttributeMaxDynamicSharedMemorySize, DYN_SMEM);
    cudaFuncSetAttribute(build_w_mma_kernel, cudaFuncAttributeMaxDynamicSharedMemorySize, WDYN);

    init_small<<<1, 32>>>();
    dim3 gt(NN / 64, NN / 64);
    split_at_kernel<<<gt, 256>>>(A);
    build_w_mma_kernel<<<136, 256, WDYN>>>(S, m_raw);
    dim3 gv(NN / TMW, BB / TMW);
    build_vx_kernel<<<gv, 256>>>(U, b, x);
    solve_kernel<<<SB, 256, DYN_SMEM>>>(out);
}